// round 5
// baseline (speedup 1.0000x reference)
#include <cuda_runtime.h>
#include <cub/cub.cuh>

// ---------------------------------------------------------------------------
// SparseWindowPartitionLayer — full GPU pipeline, graph-capturable.
//
// Constants derived from the reference:
//   SPARSE_SHAPE=(400,400,16), WINDOW_SHAPE=(10,10,4)
//   mx=my=41, mz=5, mper=8405, batches∈{0,1}  =>  win id < 16810
//   BATCHING: cnt<16 -> T=16 (lvl0); cnt<32 -> T=32 (lvl1); else T=48 (lvl2)
//   FEAT_DIM=192, pos_length=64 per axis, inv_freq[j]=1000^(j/32) (paired)
// ---------------------------------------------------------------------------

#define NV    300000
#define WMAX  16810
#define SENT  32767u

// ---- static device scratch (no runtime allocation allowed) ----------------
__device__ int          g_W0[NV], g_W1[NV];
__device__ unsigned int g_keysin[NV];
__device__ int          g_valsin[NV];
__device__ unsigned int g_sAk[NV], g_sBk[NV];
__device__ int          g_sAv[NV], g_sBv[NV];
__device__ int          g_keep0[NV], g_keepF[NV];
__device__ int          g_flags[NV], g_scan[NV], g_posOrig[NV];
__device__ int          g_vox0[NV], g_vox1[NV];
__device__ int          g_cnt[4 * WMAX];          // [c0 | c1 | cF0 | cF1]
__device__ int          g_startA[WMAX], g_startB[WMAX];
__device__ int          g_lvl0[WMAX], g_lvl1[WMAX];
__device__ int          g_startF0[WMAX], g_startF1[WMAX];
__device__ int          g_conti0[WMAX], g_conti1[WMAX];
__device__ int          g_nwin[6];
__device__ long long    g_off[16];
__device__ float        g_tab[400 * 192];          // 400 distinct pe rows
__device__ __align__(256) unsigned char g_cubtmp[1 << 24]; // 16 MB CUB temp

__device__ __forceinline__ int targetOf(int c) { return c < 16 ? 16 : (c < 32 ? 32 : 48); }
__device__ __forceinline__ int levelOf(int c)  { return c < 16 ? 0  : (c < 32 ? 1  : 2);  }
__device__ __forceinline__ int tokensOf(int l) { return l == 2 ? 48 : (16 << l); }

// ---- pe lookup table: 400 rows x 192 floats --------------------------------
__global__ void k_tab() {
    int t = blockIdx.x * blockDim.x + threadIdx.x;
    if (t >= 400 * 192) return;
    int row = t / 192, f = t - 192 * row;
    int cx = row % 10, cy = (row / 10) % 10, cz = row / 100;
    int axis = f / 64, k = f - 64 * axis;
    int j = k >> 1, ph = k & 1;
    float v = (axis == 0) ? (float)(cx - 5)
            : (axis == 1) ? (float)(cy - 5)
                          : (float)(cz - 2);
    float invf = (float)exp(log(1000.0) * (double)j / 32.0);
    float e = v / invf;
    g_tab[t] = ph ? cosf(e) : sinf(e);
}

// ---- window ids + c0 histogram + sort-A inputs ------------------------------
__global__ void k_wins(const int* __restrict__ coords, int n) {
    int i = blockIdx.x * blockDim.x + threadIdx.x;
    if (i >= n) return;
    int4 c = ((const int4*)coords)[i];      // (b, z, y, x)
    int b = c.x, z = c.y, y = c.z, x = c.w;
    int w0 = b * 8405 + ((x + 10) / 10) * 205 + ((y + 10) / 10) * 5 + ((z + 4) / 4);
    int w1 = b * 8405 + ((x + 5)  / 10) * 205 + ((y + 5)  / 10) * 5 + ((z + 2) / 4);
    g_W0[i] = w0;
    g_W1[i] = w1;
    g_keysin[i] = (unsigned)w0;
    g_valsin[i] = i;
    if ((unsigned)w0 < WMAX) atomicAdd(&g_cnt[w0], 1);
}

// ---- segment starts in a sorted key array ----------------------------------
__global__ void k_marks(int which, int n) {
    int p = blockIdx.x * blockDim.x + threadIdx.x;
    if (p >= n) return;
    const unsigned* keys = which ? g_sBk : g_sAk;
    int*           starts = which ? g_startB : g_startA;
    unsigned k = keys[p];
    if (k < WMAX && (p == 0 || keys[p - 1] != k)) starts[k] = p;
}

__global__ void k_keep0(int n) {
    int p = blockIdx.x * blockDim.x + threadIdx.x;
    if (p >= n) return;
    unsigned w = g_sAk[p];
    int i = g_sAv[p];
    int rank = p - g_startA[w];
    g_keep0[i] = (rank < targetOf(g_cnt[w])) ? 1 : 0;
}

__global__ void k_hist1(int n) {
    int i = blockIdx.x * blockDim.x + threadIdx.x;
    if (i >= n) return;
    int kp = g_keep0[i];
    int w1 = g_W1[i];
    g_keysin[i] = kp ? (unsigned)w1 : SENT;
    g_valsin[i] = i;
    if (kp) atomicAdd(&g_cnt[WMAX + w1], 1);
}

__global__ void k_keep1(int n) {
    int p = blockIdx.x * blockDim.x + threadIdx.x;
    if (p >= n) return;
    unsigned w = g_sBk[p];
    int i = g_sBv[p];
    if (w >= WMAX) { g_keepF[i] = 0; return; }
    int rank = p - g_startB[w];
    g_keepF[i] = (rank < targetOf(g_cnt[WMAX + w])) ? 1 : 0;
}

__global__ void k_lvls() {
    int w = blockIdx.x * blockDim.x + threadIdx.x;
    if (w >= WMAX) return;
    g_lvl0[w] = levelOf(g_cnt[w]);
    g_lvl1[w] = levelOf(g_cnt[WMAX + w]);
}

__global__ void k_histF(int n) {
    int i = blockIdx.x * blockDim.x + threadIdx.x;
    if (i >= n) return;
    if (g_keepF[i]) {
        atomicAdd(&g_cnt[2 * WMAX + g_W0[i]], 1);
        atomicAdd(&g_cnt[3 * WMAX + g_W1[i]], 1);
    }
}

__global__ void k_flags(int which, int n) {
    int p = blockIdx.x * blockDim.x + threadIdx.x;
    if (p >= n) return;
    const int* vals = which ? g_sBv : g_sAv;
    g_flags[p] = g_keepF[vals[p]];
}

__global__ void k_scatter(int which, int n) {
    int p = blockIdx.x * blockDim.x + threadIdx.x;
    if (p >= n) return;
    if (!g_flags[p]) return;
    const int* vals = which ? g_sBv : g_sAv;
    int*       vox  = which ? g_vox1 : g_vox0;
    vox[g_scan[p]] = vals[p];
}

// ---- fused single-block scan over windows: startF, conti (per level), nwin --
__global__ void k_winscan(int s) {
    __shared__ int4 sh[1024];
    const int* cF  = &g_cnt[(2 + s) * WMAX];
    const int* lvl = s ? g_lvl1 : g_lvl0;
    int* startF = s ? g_startF1 : g_startF0;
    int* conti  = s ? g_conti1  : g_conti0;
    int tid = threadIdx.x;
    int4 carry = make_int4(0, 0, 0, 0);
    for (int base = 0; base < WMAX; base += 1024) {
        int w = base + tid;
        int c = 0, l = 0;
        if (w < WMAX) { c = cF[w]; l = lvl[w]; }
        int occ = (c > 0) ? 1 : 0;
        int4 v = make_int4(c, (occ && l == 0) ? 1 : 0,
                              (occ && l == 1) ? 1 : 0,
                              (occ && l == 2) ? 1 : 0);
        sh[tid] = v;
        __syncthreads();
        for (int off = 1; off < 1024; off <<= 1) {
            int4 t = sh[tid];
            int4 a = make_int4(0, 0, 0, 0);
            if (tid >= off) a = sh[tid - off];
            __syncthreads();
            t.x += a.x; t.y += a.y; t.z += a.z; t.w += a.w;
            sh[tid] = t;
            __syncthreads();
        }
        int4 incl = sh[tid];
        if (w < WMAX) {
            startF[w] = incl.x - v.x + carry.x;
            int ey = incl.y - v.y + carry.y;
            int ez = incl.z - v.z + carry.z;
            int ew = incl.w - v.w + carry.w;
            conti[w] = (l == 0) ? ey : (l == 1) ? ez : ew;
        }
        int4 last = sh[1023];
        carry.x += last.x; carry.y += last.y; carry.z += last.z; carry.w += last.w;
        __syncthreads();
    }
    if (tid == 0) {
        g_nwin[3 * s + 0] = carry.y;
        g_nwin[3 * s + 1] = carry.z;
        g_nwin[3 * s + 2] = carry.w;
    }
}

// ---- output segment offsets (floats) ----------------------------------------
__global__ void k_offsets(int n) {
    long long M = (long long)g_posOrig[n - 1] + g_keepF[n - 1];
    long long o = 0;
    g_off[0] = 0;       o = M * 192;          // feats
    g_off[1] = o;       o += M * 4;           // coords
    const int T[3] = {16, 32, 48};
    for (int s = 0; s < 2; s++) {
        for (int d = 0; d < 3; d++) { g_off[2 + 6 * s + d] = o; o += (long long)g_nwin[3 * s + d] * T[d] * 192; }
        for (int d = 0; d < 3; d++) { g_off[5 + 6 * s + d] = o; o += (long long)g_nwin[3 * s + d] * T[d]; }
    }
    g_off[14] = o;  // total (debug)
}

// ---- writers ----------------------------------------------------------------
__global__ void k_feats(const float4* __restrict__ fin, float4* __restrict__ out, int n) {
    int idx = blockIdx.x * blockDim.x + threadIdx.x;
    int i = idx / 48, c = idx - 48 * i;
    if (i >= n) return;
    if (!g_keepF[i]) return;
    long long pos = g_posOrig[i];
    out[pos * 48 + c] = fin[(long long)i * 48 + c];
}

__global__ void k_coords(const int* __restrict__ coords, float* __restrict__ out, int n) {
    int i = blockIdx.x * blockDim.x + threadIdx.x;
    if (i >= n) return;
    if (!g_keepF[i]) return;
    long long pos = g_posOrig[i];
    int4 c = ((const int4*)coords)[i];
    float4* o = (float4*)(out + g_off[1]);
    o[pos] = make_float4((float)c.x, (float)c.y, (float)c.z, (float)c.w);
}

// one block per window: writes its pe rows (incl. zero padding) and mask row
__global__ void k_pe(const int* __restrict__ coords, float* __restrict__ out, int s) {
    int w = blockIdx.x;
    int cnt = g_cnt[(2 + s) * WMAX + w];
    if (cnt == 0) return;   // window not occupied in final set
    int l     = s ? g_lvl1[w]    : g_lvl0[w];
    int conti = s ? g_conti1[w]  : g_conti0[w];
    int start = s ? g_startF1[w] : g_startF0[w];
    const int* vox = s ? g_vox1 : g_vox0;
    int T = tokensOf(l);
    long long pebase   = g_off[2 + 6 * s + l] + (long long)conti * T * 192;
    long long maskbase = g_off[5 + 6 * s + l] + (long long)conti * T;

    __shared__ int rowtab[48];
    int t = threadIdx.x;
    if (t < T) {
        int tb = -1;
        if (t < cnt) {
            int v = vox[start + t];
            int z = coords[4 * v + 1], y = coords[4 * v + 2], x = coords[4 * v + 3];
            int cx, cy, cz;
            if (s == 0) { cx = (x + 10) % 10; cy = (y + 10) % 10; cz = (z + 4) % 4; }
            else        { cx = (x + 5)  % 10; cy = (y + 5)  % 10; cz = (z + 2) % 4; }
            tb = (cz * 10 + cy) * 10 + cx;
        }
        rowtab[t] = tb;
        out[maskbase + t] = (t >= cnt) ? 1.0f : 0.0f;   // key_padding_mask
    }
    __syncthreads();

    const float4* tab4 = (const float4*)g_tab;
    float4* o4 = (float4*)(out + pebase);
    int tot4 = T * 48;
    for (int j = t; j < tot4; j += blockDim.x) {
        int tt = j / 48, f4 = j - 48 * tt;
        int tb = rowtab[tt];
        o4[j] = (tb >= 0) ? tab4[tb * 48 + f4] : make_float4(0.f, 0.f, 0.f, 0.f);
    }
}

// ---------------------------------------------------------------------------
extern "C" void kernel_launch(void* const* d_in, const int* in_sizes, int n_in,
                              void* d_out, int out_size) {
    const float* feats  = (const float*)d_in[0];
    const int*   coords = (const int*)d_in[1];
    float* out = (float*)d_out;

    int n = in_sizes[1] / 4;
    if (n > NV) n = NV;
    int nb = (n + 255) / 256;

    void *p_cnt, *p_tmp, *p_ki, *p_vi, *p_sAk, *p_sAv, *p_sBk, *p_sBv;
    void *p_keepF, *p_pos, *p_flags, *p_scan;
    cudaGetSymbolAddress(&p_cnt,   g_cnt);
    cudaGetSymbolAddress(&p_tmp,   g_cubtmp);
    cudaGetSymbolAddress(&p_ki,    g_keysin);
    cudaGetSymbolAddress(&p_vi,    g_valsin);
    cudaGetSymbolAddress(&p_sAk,   g_sAk);
    cudaGetSymbolAddress(&p_sAv,   g_sAv);
    cudaGetSymbolAddress(&p_sBk,   g_sBk);
    cudaGetSymbolAddress(&p_sBv,   g_sBv);
    cudaGetSymbolAddress(&p_keepF, g_keepF);
    cudaGetSymbolAddress(&p_pos,   g_posOrig);
    cudaGetSymbolAddress(&p_flags, g_flags);
    cudaGetSymbolAddress(&p_scan,  g_scan);

    size_t cap;

    cudaMemsetAsync(p_cnt, 0, sizeof(int) * 4 * WMAX);
    k_tab<<<(400 * 192 + 255) / 256, 256>>>();
    k_wins<<<nb, 256>>>(coords, n);

    // stable sort A: (W0, idx) over all voxels
    cap = sizeof(g_cubtmp);
    cub::DeviceRadixSort::SortPairs(p_tmp, cap,
        (const unsigned*)p_ki, (unsigned*)p_sAk,
        (const int*)p_vi, (int*)p_sAv, n, 0, 15);
    k_marks<<<nb, 256>>>(0, n);
    k_keep0<<<nb, 256>>>(n);

    // c1 histogram over kept0 + sort-B inputs (sentinel for dropped)
    k_hist1<<<nb, 256>>>(n);
    cap = sizeof(g_cubtmp);
    cub::DeviceRadixSort::SortPairs(p_tmp, cap,
        (const unsigned*)p_ki, (unsigned*)p_sBk,
        (const int*)p_vi, (int*)p_sBv, n, 0, 15);
    k_marks<<<nb, 256>>>(1, n);
    k_keep1<<<nb, 256>>>(n);

    k_lvls<<<(WMAX + 255) / 256, 256>>>();
    k_histF<<<nb, 256>>>(n);

    // compacted positions in original order (for feats/coords)
    cap = sizeof(g_cubtmp);
    cub::DeviceScan::ExclusiveSum(p_tmp, cap, (const int*)p_keepF, (int*)p_pos, n);

    // grouped final voxel lists per shift (stable, window-grouped)
    k_flags<<<nb, 256>>>(0, n);
    cap = sizeof(g_cubtmp);
    cub::DeviceScan::ExclusiveSum(p_tmp, cap, (const int*)p_flags, (int*)p_scan, n);
    k_scatter<<<nb, 256>>>(0, n);

    k_flags<<<nb, 256>>>(1, n);
    cap = sizeof(g_cubtmp);
    cub::DeviceScan::ExclusiveSum(p_tmp, cap, (const int*)p_flags, (int*)p_scan, n);
    k_scatter<<<nb, 256>>>(1, n);

    // per-window metadata and output offsets
    k_winscan<<<1, 1024>>>(0);
    k_winscan<<<1, 1024>>>(1);
    k_offsets<<<1, 1>>>(n);

    // output writers
    k_feats<<<(n * 48 + 255) / 256, 256>>>((const float4*)feats, (float4*)out, n);
    k_coords<<<nb, 256>>>(coords, out, n);
    k_pe<<<WMAX, 256>>>(coords, out, 0);
    k_pe<<<WMAX, 256>>>(coords, out, 1);
}

// round 6
// speedup vs baseline: 1.2604x; 1.2604x over previous
#include <cuda_runtime.h>
#include <cub/cub.cuh>

// ---------------------------------------------------------------------------
// SparseWindowPartitionLayer — full GPU pipeline, graph-capturable.
//   SPARSE_SHAPE=(400,400,16), WINDOW_SHAPE=(10,10,4)
//   mx=my=41, mz=5, mper=8405, batch in {0,1}  =>  win id < 16810
//   cnt<16 -> T=16 (lvl0); cnt<32 -> T=32 (lvl1); else T=48 (lvl2)
//   FEAT_DIM=192; pe depends only on in-window coords => 400-row LUT
// ---------------------------------------------------------------------------

#define NV    300000
#define WMAX  16810
#define SENT  32767u

// ---- static device scratch --------------------------------------------------
__device__ int          g_W0[NV], g_W1[NV];
__device__ int          g_tb[NV];               // tb0 | tb1<<16 (pe table rows)
__device__ unsigned     g_keysin[NV];
__device__ int          g_valsin[NV];
__device__ unsigned     g_sAk[NV], g_sBk[NV];
__device__ int          g_sAv[NV], g_sBv[NV];
__device__ int          g_keepF[NV];
__device__ int          g_srcOf[NV];            // output pos -> original voxel
__device__ int          g_vox0[NV], g_vox1[NV]; // grouped tb values per shift
__device__ int          g_cnt[4 * WMAX];        // [c0 | c1 | cF0 | cF1]
__device__ int          g_startA[WMAX], g_startB[WMAX];
__device__ int          g_lvl0[WMAX], g_lvl1[WMAX];
__device__ int          g_startF0[WMAX], g_startF1[WMAX];
__device__ int          g_conti0[WMAX], g_conti1[WMAX];
__device__ int          g_nwin[6];
__device__ int          g_total;
__device__ long long    g_off[16];
__device__ float        g_tab[400 * 192];
__device__ unsigned long long g_status[3 * 256];
__device__ int          g_ticket[4];
__device__ __align__(256) unsigned char g_cubtmp[1 << 24];

__device__ __forceinline__ int targetOf(int c) { return c < 16 ? 16 : (c < 32 ? 32 : 48); }
__device__ __forceinline__ int levelOf(int c)  { return c < 16 ? 0  : (c < 32 ? 1  : 2);  }
__device__ __forceinline__ int tokensOf(int l) { return l == 2 ? 48 : (16 << l); }

// ---- pe LUT + zero all counters/statuses (replaces a memset node) ----------
__global__ void k_tab() {
    int t = blockIdx.x * blockDim.x + threadIdx.x;
    if (t < 4 * WMAX) g_cnt[t] = 0;
    if (t < 3 * 256)  g_status[t] = 0ull;
    if (t < 4)        g_ticket[t] = 0;
    if (t >= 400 * 192) return;
    int row = t / 192, f = t - 192 * row;
    int cx = row % 10, cy = (row / 10) % 10, cz = row / 100;
    int axis = f / 64, k = f - 64 * axis;
    int j = k >> 1, ph = k & 1;
    float v = (axis == 0) ? (float)(cx - 5)
            : (axis == 1) ? (float)(cy - 5)
                          : (float)(cz - 2);
    float invf = (float)exp(log(1000.0) * (double)j / 32.0);
    float e = v / invf;
    g_tab[t] = ph ? cosf(e) : sinf(e);
}

// ---- window ids + c0 histogram + sort-A inputs + pe row ids ----------------
__global__ void k_wins(const int* __restrict__ coords, int n) {
    int i = blockIdx.x * blockDim.x + threadIdx.x;
    if (i >= n) return;
    int4 c = ((const int4*)coords)[i];      // (b, z, y, x)
    int b = c.x, z = c.y, y = c.z, x = c.w;
    int w0 = b * 8405 + ((x + 10) / 10) * 205 + ((y + 10) / 10) * 5 + ((z + 4) / 4);
    int w1 = b * 8405 + ((x + 5)  / 10) * 205 + ((y + 5)  / 10) * 5 + ((z + 2) / 4);
    g_W0[i] = w0;
    g_W1[i] = w1;
    int tb0 = ((z % 4) * 10 + (y % 10)) * 10 + (x % 10);
    int tb1 = (((z + 2) % 4) * 10 + ((y + 5) % 10)) * 10 + ((x + 5) % 10);
    g_tb[i] = tb0 | (tb1 << 16);
    g_keysin[i] = (unsigned)w0;
    g_valsin[i] = i;
    atomicAdd(&g_cnt[w0], 1);
}

// ---- single-block exclusive scan over WMAX counters -------------------------
__global__ void k_exscan(const int* __restrict__ in, int* __restrict__ out) {
    __shared__ int ws[32];
    int tid = threadIdx.x, lane = tid & 31, warp = tid >> 5;
    int carry = 0;
    for (int base = 0; base < WMAX; base += 1024) {
        int w = base + tid;
        int v = (w < WMAX) ? in[w] : 0;
        int x = v;
        #pragma unroll
        for (int o = 1; o < 32; o <<= 1) { int y = __shfl_up_sync(~0u, x, o); if (lane >= o) x += y; }
        if (lane == 31) ws[warp] = x;
        __syncthreads();
        if (warp == 0) {
            int y = ws[lane];
            #pragma unroll
            for (int o = 1; o < 32; o <<= 1) { int z = __shfl_up_sync(~0u, y, o); if (lane >= o) y += z; }
            ws[lane] = y;
        }
        __syncthreads();
        int excl = x - v + (warp ? ws[warp - 1] : 0) + carry;
        if (w < WMAX) out[w] = excl;
        carry += ws[31];
        __syncthreads();
    }
}

// ---- keep0 + c1 histogram + sort-B keys (fused) -----------------------------
__global__ void k_keep0f(int n) {
    int p = blockIdx.x * blockDim.x + threadIdx.x;
    if (p >= n) return;
    unsigned w = g_sAk[p];
    int i = g_sAv[p];
    int rank = p - g_startA[w];
    int keep = rank < targetOf(g_cnt[w]);
    if (keep) {
        int w1 = g_W1[i];
        g_keysin[i] = (unsigned)w1;
        atomicAdd(&g_cnt[WMAX + w1], 1);
    } else {
        g_keysin[i] = SENT;
    }
}

// ---- keepF + final histograms (fused) ---------------------------------------
__global__ void k_keep1f(int n) {
    int p = blockIdx.x * blockDim.x + threadIdx.x;
    if (p >= n) return;
    unsigned w = g_sBk[p];
    int i = g_sBv[p];
    if (w >= WMAX) { g_keepF[i] = 0; return; }
    int rank = p - g_startB[w];
    int kf = rank < targetOf(g_cnt[WMAX + w]);
    g_keepF[i] = kf;
    if (kf) {
        atomicAdd(&g_cnt[2 * WMAX + g_W0[i]], 1);
        atomicAdd(&g_cnt[3 * WMAX + w], 1);
    }
}

// ---- meta: per-window startF/conti/lvl, nwin, total, output offsets ---------
__global__ void k_meta() {
    __shared__ int ws0[32], ws1[32], ws2[32], ws3[32];
    int tid = threadIdx.x, lane = tid & 31, warp = tid >> 5;
    int M0 = 0;
    for (int s = 0; s < 2; s++) {
        const int* cF = &g_cnt[(2 + s) * WMAX];
        const int* cL = &g_cnt[s * WMAX];
        int* lvlArr   = s ? g_lvl1    : g_lvl0;
        int* startArr = s ? g_startF1 : g_startF0;
        int* contArr  = s ? g_conti1  : g_conti0;
        int c0 = 0, c1 = 0, c2 = 0, c3 = 0;
        for (int base = 0; base < WMAX; base += 1024) {
            int w = base + tid;
            int cf = 0, l = 0;
            if (w < WMAX) { cf = cF[w]; l = levelOf(cL[w]); }
            int occ = cf > 0;
            int v0 = cf;
            int v1 = (occ && l == 0) ? 1 : 0;
            int v2 = (occ && l == 1) ? 1 : 0;
            int v3 = (occ && l == 2) ? 1 : 0;
            int x0 = v0, x1 = v1, x2 = v2, x3 = v3;
            #pragma unroll
            for (int o = 1; o < 32; o <<= 1) {
                int y0 = __shfl_up_sync(~0u, x0, o);
                int y1 = __shfl_up_sync(~0u, x1, o);
                int y2 = __shfl_up_sync(~0u, x2, o);
                int y3 = __shfl_up_sync(~0u, x3, o);
                if (lane >= o) { x0 += y0; x1 += y1; x2 += y2; x3 += y3; }
            }
            if (lane == 31) { ws0[warp] = x0; ws1[warp] = x1; ws2[warp] = x2; ws3[warp] = x3; }
            __syncthreads();
            if (warp == 0) {
                int y0 = ws0[lane], y1 = ws1[lane], y2 = ws2[lane], y3 = ws3[lane];
                #pragma unroll
                for (int o = 1; o < 32; o <<= 1) {
                    int z0 = __shfl_up_sync(~0u, y0, o);
                    int z1 = __shfl_up_sync(~0u, y1, o);
                    int z2 = __shfl_up_sync(~0u, y2, o);
                    int z3 = __shfl_up_sync(~0u, y3, o);
                    if (lane >= o) { y0 += z0; y1 += z1; y2 += z2; y3 += z3; }
                }
                ws0[lane] = y0; ws1[lane] = y1; ws2[lane] = y2; ws3[lane] = y3;
            }
            __syncthreads();
            int b0 = warp ? ws0[warp - 1] : 0;
            int b1 = warp ? ws1[warp - 1] : 0;
            int b2 = warp ? ws2[warp - 1] : 0;
            int b3 = warp ? ws3[warp - 1] : 0;
            if (w < WMAX) {
                lvlArr[w]   = l;
                startArr[w] = x0 - v0 + b0 + c0;
                int e1 = x1 - v1 + b1 + c1;
                int e2 = x2 - v2 + b2 + c2;
                int e3 = x3 - v3 + b3 + c3;
                contArr[w]  = (l == 0) ? e1 : (l == 1) ? e2 : e3;
            }
            c0 += ws0[31]; c1 += ws1[31]; c2 += ws2[31]; c3 += ws3[31];
            __syncthreads();
        }
        if (tid == 0) {
            g_nwin[3 * s + 0] = c1;
            g_nwin[3 * s + 1] = c2;
            g_nwin[3 * s + 2] = c3;
        }
        if (s == 0) M0 = c0;
        __syncthreads();
    }
    if (tid == 0) {
        g_total = M0;
        long long M = M0;
        long long o = 0;
        g_off[0] = 0;       o = M * 192;          // feats
        g_off[1] = o;       o += M * 4;           // coords
        const int T[3] = {16, 32, 48};
        for (int s = 0; s < 2; s++) {
            for (int d = 0; d < 3; d++) { g_off[2 + 6 * s + d] = o; o += (long long)g_nwin[3 * s + d] * T[d] * 192; }
            for (int d = 0; d < 3; d++) { g_off[5 + 6 * s + d] = o; o += (long long)g_nwin[3 * s + d] * T[d]; }
        }
        g_off[14] = o;
    }
}

// ---- single-pass decoupled-lookback stream compaction ------------------------
// MODE 0: flag=keepF[p], value=p            -> g_srcOf
// MODE 1: i=sAv[p], flag=keepF[i], v=tb0    -> g_vox0
// MODE 2: i=sBv[p], flag=keepF[i], v=tb1    -> g_vox1
#define SEL_THREADS 256
#define SEL_ITEMS   8
#define SEL_TILE    (SEL_THREADS * SEL_ITEMS)

template <int MODE>
__global__ void k_select(int n) {
    __shared__ int s_bid;
    __shared__ int s_wsum[8];
    __shared__ int s_base;
    unsigned long long* status = g_status + MODE * 256;
    if (threadIdx.x == 0) s_bid = atomicAdd(&g_ticket[MODE], 1);
    __syncthreads();
    int bid = s_bid;
    int base = bid * SEL_TILE;

    int flags[SEL_ITEMS], vals[SEL_ITEMS];
    int cnt = 0;
    #pragma unroll
    for (int k = 0; k < SEL_ITEMS; k++) {
        int p = base + threadIdx.x * SEL_ITEMS + k;
        int f = 0, v = 0;
        if (p < n) {
            if (MODE == 0)      { f = g_keepF[p]; v = p; }
            else if (MODE == 1) { int i = g_sAv[p]; f = g_keepF[i]; v = g_tb[i] & 0xFFFF; }
            else                { int i = g_sBv[p]; f = g_keepF[i]; v = g_tb[i] >> 16; }
        }
        flags[k] = f; vals[k] = v; cnt += f;
    }
    int lane = threadIdx.x & 31, warp = threadIdx.x >> 5;
    int x = cnt;
    #pragma unroll
    for (int o = 1; o < 32; o <<= 1) { int y = __shfl_up_sync(~0u, x, o); if (lane >= o) x += y; }
    if (lane == 31) s_wsum[warp] = x;
    __syncthreads();
    if (threadIdx.x < 8) {
        int y = s_wsum[threadIdx.x];
        #pragma unroll
        for (int o = 1; o < 8; o <<= 1) { int z = __shfl_up_sync(0xFFu, y, o); if ((int)threadIdx.x >= o) y += z; }
        s_wsum[threadIdx.x] = y;
    }
    __syncthreads();
    int blockAgg   = s_wsum[7];
    int threadExcl = x - cnt + (warp ? s_wsum[warp - 1] : 0);

    if (threadIdx.x == 0) {
        if (bid == 0) {
            atomicExch(&status[0], ((unsigned long long)blockAgg << 2) | 2ull);
            s_base = 0;
        } else {
            atomicExch(&status[bid], ((unsigned long long)blockAgg << 2) | 1ull);
            int excl = 0;
            int look = bid - 1;
            while (true) {
                unsigned long long s;
                do { s = atomicAdd(&status[look], 0ull); } while ((s & 3ull) == 0ull);
                excl += (int)(s >> 2);
                if ((s & 3ull) == 2ull) break;
                look--;
            }
            atomicExch(&status[bid], ((unsigned long long)(excl + blockAgg) << 2) | 2ull);
            s_base = excl;
        }
    }
    __syncthreads();
    int pos = s_base + threadExcl;
    int* out = (MODE == 0) ? g_srcOf : (MODE == 1) ? g_vox0 : g_vox1;
    #pragma unroll
    for (int k = 0; k < SEL_ITEMS; k++) {
        if (flags[k]) out[pos++] = vals[k];
    }
}

// ---- writers: feats (gather by srcOf) + coords fused -------------------------
__global__ void k_feats(const float4* __restrict__ fin, const int* __restrict__ coords,
                        float* __restrict__ out) {
    int M = g_total;
    int idx = blockIdx.x * blockDim.x + threadIdx.x;
    int pos = idx / 48, c = idx - 48 * pos;
    if (pos >= M) return;
    int src = g_srcOf[pos];
    float4 v = __ldcs(&fin[(long long)src * 48 + c]);
    __stcs(&((float4*)out)[(long long)pos * 48 + c], v);
    if (c == 0) {
        int4 cc = ((const int4*)coords)[src];
        float4* oc = (float4*)(out + g_off[1]);
        __stcs(&oc[pos], make_float4((float)cc.x, (float)cc.y, (float)cc.z, (float)cc.w));
    }
}

// ---- pe + mask writer: one block per window ----------------------------------
__global__ void k_pe(float* __restrict__ out, int s) {
    int w = blockIdx.x;
    int cnt = g_cnt[(2 + s) * WMAX + w];
    if (cnt == 0) return;
    int l     = s ? g_lvl1[w]    : g_lvl0[w];
    int conti = s ? g_conti1[w]  : g_conti0[w];
    int start = s ? g_startF1[w] : g_startF0[w];
    const int* vox = s ? g_vox1 : g_vox0;
    int T = tokensOf(l);
    long long pebase   = g_off[2 + 6 * s + l] + (long long)conti * T * 192;
    long long maskbase = g_off[5 + 6 * s + l] + (long long)conti * T;

    __shared__ int rowtab[48];
    int t = threadIdx.x;
    if (t < T) {
        rowtab[t] = (t < cnt) ? vox[start + t] : -1;
        __stcs(&out[maskbase + t], (t >= cnt) ? 1.0f : 0.0f);
    }
    __syncthreads();

    const float4* tab4 = (const float4*)g_tab;
    float4* o4 = (float4*)(out + pebase);
    int tot4 = T * 48;
    for (int j = t; j < tot4; j += blockDim.x) {
        int tt = j / 48, f4 = j - 48 * tt;
        int tb = rowtab[tt];
        float4 v = (tb >= 0) ? __ldg(&tab4[tb * 48 + f4]) : make_float4(0.f, 0.f, 0.f, 0.f);
        __stcs(&o4[j], v);
    }
}

// ---------------------------------------------------------------------------
extern "C" void kernel_launch(void* const* d_in, const int* in_sizes, int n_in,
                              void* d_out, int out_size) {
    const float* feats  = (const float*)d_in[0];
    const int*   coords = (const int*)d_in[1];
    float* out = (float*)d_out;

    int n = in_sizes[1] / 4;
    if (n > NV) n = NV;
    int nb = (n + 255) / 256;

    void *p_tmp, *p_ki, *p_vi, *p_sAk, *p_sAv, *p_sBk, *p_sBv;
    void *p_cnt0, *p_cnt1, *p_stA, *p_stB;
    cudaGetSymbolAddress(&p_tmp, g_cubtmp);
    cudaGetSymbolAddress(&p_ki,  g_keysin);
    cudaGetSymbolAddress(&p_vi,  g_valsin);
    cudaGetSymbolAddress(&p_sAk, g_sAk);
    cudaGetSymbolAddress(&p_sAv, g_sAv);
    cudaGetSymbolAddress(&p_sBk, g_sBk);
    cudaGetSymbolAddress(&p_sBv, g_sBv);
    cudaGetSymbolAddress(&p_cnt0, g_cnt);
    p_cnt1 = (char*)p_cnt0 + sizeof(int) * WMAX;
    cudaGetSymbolAddress(&p_stA, g_startA);
    cudaGetSymbolAddress(&p_stB, g_startB);

    size_t cap;

    k_tab<<<(400 * 192 + 255) / 256, 256>>>();          // also zeroes cnt/status/ticket
    k_wins<<<nb, 256>>>(coords, n);
    k_exscan<<<1, 1024>>>((const int*)p_cnt0, (int*)p_stA);

    cap = sizeof(g_cubtmp);
    cub::DeviceRadixSort::SortPairs(p_tmp, cap,
        (const unsigned*)p_ki, (unsigned*)p_sAk,
        (const int*)p_vi, (int*)p_sAv, n, 0, 15);

    k_keep0f<<<nb, 256>>>(n);
    k_exscan<<<1, 1024>>>((const int*)p_cnt1, (int*)p_stB);

    cap = sizeof(g_cubtmp);
    cub::DeviceRadixSort::SortPairs(p_tmp, cap,
        (const unsigned*)p_ki, (unsigned*)p_sBk,
        (const int*)p_vi, (int*)p_sBv, n, 0, 15);

    k_keep1f<<<nb, 256>>>(n);
    k_meta<<<1, 1024>>>();

    int selblk = (n + SEL_TILE - 1) / SEL_TILE;
    k_select<0><<<selblk, SEL_THREADS>>>(n);
    k_select<1><<<selblk, SEL_THREADS>>>(n);
    k_select<2><<<selblk, SEL_THREADS>>>(n);

    k_feats<<<(n * 48 + 255) / 256, 256>>>((const float4*)feats, coords, out);
    k_pe<<<WMAX, 256>>>(out, 0);
    k_pe<<<WMAX, 256>>>(out, 1);
}

// round 8
// speedup vs baseline: 1.5514x; 1.2309x over previous
#include <cuda_runtime.h>

// ---------------------------------------------------------------------------
// SparseWindowPartitionLayer — full GPU pipeline, graph-capturable, no CUB.
//   win id < 16810; T=16/32/48 by pre-drop window count; FEAT_DIM=192
//   pe depends only on in-window coords => 400-row LUT (L2 resident)
//   Stable per-window order = atomic scatter into histogrammed segments,
//   then per-window warp sort by original voxel index.
// ---------------------------------------------------------------------------

#define NV    300000
#define WMAX  16810

__device__ int  g_W0[NV], g_W1[NV], g_tb[NV];   // tb0 | tb1<<16
__device__ int  g_arrA[NV], g_arrB[NV];         // window-grouped voxel ids
__device__ int  g_keep0[NV], g_keepF[NV], g_srcOf[NV];
__device__ int  g_cnt0[WMAX], g_cnt1[WMAX], g_cntF0[WMAX];
__device__ int  g_startA[WMAX], g_startB[WMAX]; // excl-scan, bumped to seg end
__device__ int  g_lvl0[WMAX], g_lvl1[WMAX], g_conti0[WMAX], g_conti1[WMAX];
__device__ int  g_nwin[6], g_total;
__device__ long long g_off[16];
__device__ float g_tab[400 * 192];
__device__ unsigned long long g_status[256];
__device__ int  g_ticket;

__device__ __forceinline__ int targetOf(int c) { return c < 16 ? 16 : (c < 32 ? 32 : 48); }
__device__ __forceinline__ int levelOf(int c)  { return c < 16 ? 0  : (c < 32 ? 1  : 2);  }
__device__ __forceinline__ int tokensOf(int l) { return l == 2 ? 48 : (16 << l); }

// ---- pe LUT + zero all counters/status ---------------------------------------
__global__ void k_tab() {
    int t = blockIdx.x * blockDim.x + threadIdx.x;
    if (t < WMAX) { g_cnt0[t] = 0; g_cnt1[t] = 0; g_cntF0[t] = 0; }
    if (t < 256)  g_status[t] = 0ull;
    if (t == 0)   g_ticket = 0;
    if (t >= 400 * 192) return;
    int row = t / 192, f = t - 192 * row;
    int cx = row % 10, cy = (row / 10) % 10, cz = row / 100;
    int axis = f / 64, k = f - 64 * axis;
    int j = k >> 1, ph = k & 1;
    float v = (axis == 0) ? (float)(cx - 5)
            : (axis == 1) ? (float)(cy - 5)
                          : (float)(cz - 2);
    float invf = (float)exp(log(1000.0) * (double)j / 32.0);
    float e = v / invf;
    g_tab[t] = ph ? cosf(e) : sinf(e);
}

// ---- window ids + c0 histogram + pe row ids -----------------------------------
__global__ void k_wins(const int* __restrict__ coords, int n) {
    int i = blockIdx.x * blockDim.x + threadIdx.x;
    if (i >= n) return;
    int4 c = ((const int4*)coords)[i];      // (b, z, y, x)
    int b = c.x, z = c.y, y = c.z, x = c.w;
    int w0 = b * 8405 + ((x + 10) / 10) * 205 + ((y + 10) / 10) * 5 + ((z + 4) / 4);
    int w1 = b * 8405 + ((x + 5)  / 10) * 205 + ((y + 5)  / 10) * 5 + ((z + 2) / 4);
    g_W0[i] = w0;
    g_W1[i] = w1;
    int tb0 = ((z % 4) * 10 + (y % 10)) * 10 + (x % 10);
    int tb1 = (((z + 2) % 4) * 10 + ((y + 5) % 10)) * 10 + ((x + 5) % 10);
    g_tb[i] = tb0 | (tb1 << 16);
    atomicAdd(&g_cnt0[w0], 1);
}

// ---- single-block exclusive scan over WMAX counters ---------------------------
__global__ void k_exscan(const int* __restrict__ in, int* __restrict__ out) {
    __shared__ int ws[32];
    int tid = threadIdx.x, lane = tid & 31, warp = tid >> 5;
    int carry = 0;
    for (int base = 0; base < WMAX; base += 1024) {
        int w = base + tid;
        int v = (w < WMAX) ? in[w] : 0;
        int x = v;
        #pragma unroll
        for (int o = 1; o < 32; o <<= 1) { int y = __shfl_up_sync(~0u, x, o); if (lane >= o) x += y; }
        if (lane == 31) ws[warp] = x;
        __syncthreads();
        if (warp == 0) {
            int y = ws[lane];
            #pragma unroll
            for (int o = 1; o < 32; o <<= 1) { int z = __shfl_up_sync(~0u, y, o); if (lane >= o) y += z; }
            ws[lane] = y;
        }
        __syncthreads();
        int excl = x - v + (warp ? ws[warp - 1] : 0) + carry;
        if (w < WMAX) out[w] = excl;
        carry += ws[31];
        __syncthreads();
    }
}

// ---- scatter voxels into window segments (order fixed by later sort) ----------
__global__ void k_scat0(int n) {
    int i = blockIdx.x * blockDim.x + threadIdx.x;
    if (i >= n) return;
    int pos = atomicAdd(&g_startA[g_W0[i]], 1);
    g_arrA[pos] = i;
}

__global__ void k_scat1(int n) {
    int i = blockIdx.x * blockDim.x + threadIdx.x;
    if (i >= n) return;
    if (!g_keep0[i]) return;
    int pos = atomicAdd(&g_startB[g_W1[i]], 1);
    g_arrB[pos] = i;
}

// ---- per-window warp sort (ascending voxel index = stable original order) -----
__device__ void sortSeg(int* a, int cnt, int lane) {
    if (cnt <= 128) {
        int v[4];
        #pragma unroll
        for (int r = 0; r < 4; r++) {
            int e = lane + 32 * r;
            v[r] = (e < cnt) ? a[e] : 0x7FFFFFFF;
        }
        #pragma unroll
        for (int k = 2; k <= 128; k <<= 1) {
            #pragma unroll
            for (int j = k >> 1; j > 0; j >>= 1) {
                if (j >= 32) {
                    int s = j >> 5;
                    #pragma unroll
                    for (int r = 0; r < 4; r++) {
                        int pr = r ^ s;
                        if (r < pr) {
                            bool up = (((lane + 32 * r) & k) == 0);
                            int x = v[r], y = v[pr];
                            int lo = min(x, y), hi = max(x, y);
                            v[r]  = up ? lo : hi;
                            v[pr] = up ? hi : lo;
                        }
                    }
                } else {
                    #pragma unroll
                    for (int r = 0; r < 4; r++) {
                        int e = lane + 32 * r;
                        bool up = ((e & k) == 0);
                        int o = __shfl_xor_sync(~0u, v[r], j);
                        bool lower = ((lane & j) == 0);
                        int mn = min(v[r], o), mx = max(v[r], o);
                        v[r] = (up == lower) ? mn : mx;
                    }
                }
            }
        }
        #pragma unroll
        for (int r = 0; r < 4; r++) {
            int e = lane + 32 * r;
            if (e < cnt) a[e] = v[r];
        }
    } else {
        // robust fallback (not expected for this dataset): odd-even transposition
        for (int pass = 0; pass < cnt; pass++) {
            for (int p = (pass & 1) + 2 * lane; p + 1 < cnt; p += 64) {
                int x = a[p], y = a[p + 1];
                if (x > y) { a[p] = y; a[p + 1] = x; }
            }
            __syncwarp();
            __threadfence_block();
        }
    }
    __syncwarp();
}

__global__ void k_sw0() {
    int wid = blockIdx.x * (blockDim.x >> 5) + (threadIdx.x >> 5);
    if (wid >= WMAX) return;
    int lane = threadIdx.x & 31;
    int cnt = g_cnt0[wid];
    if (cnt == 0) return;
    int seg = g_startA[wid] - cnt;
    sortSeg(g_arrA + seg, cnt, lane);
    int t = targetOf(cnt);
    for (int e = lane; e < cnt; e += 32) {
        int v = g_arrA[seg + e];
        int kp = e < t;
        g_keep0[v] = kp;
        if (kp) atomicAdd(&g_cnt1[g_W1[v]], 1);
        else    g_keepF[v] = 0;     // dropped at stage 0 => never revisited
    }
}

__global__ void k_sw1() {
    int wid = blockIdx.x * (blockDim.x >> 5) + (threadIdx.x >> 5);
    if (wid >= WMAX) return;
    int lane = threadIdx.x & 31;
    int cnt = g_cnt1[wid];
    if (cnt == 0) return;
    int seg = g_startB[wid] - cnt;
    sortSeg(g_arrB + seg, cnt, lane);
    int t = targetOf(cnt);
    for (int e = lane; e < cnt; e += 32) {
        int v = g_arrB[seg + e];
        int kf = e < t;
        g_keepF[v] = kf;
        if (kf) atomicAdd(&g_cntF0[g_W0[v]], 1);
    }
}

// ---- meta: lvl/conti per window, nwin per (shift,lvl), total, output offsets --
__global__ void k_meta() {
    __shared__ int ws0[32], ws1[32], ws2[32], ws3[32];
    int tid = threadIdx.x, lane = tid & 31, warp = tid >> 5;
    int M0 = 0;
    for (int s = 0; s < 2; s++) {
        int* lvlArr  = s ? g_lvl1   : g_lvl0;
        int* contArr = s ? g_conti1 : g_conti0;
        int c0 = 0, c1 = 0, c2 = 0, c3 = 0;
        for (int base = 0; base < WMAX; base += 1024) {
            int w = base + tid;
            int cf = 0, l = 0;
            if (w < WMAX) {
                if (s == 0) { cf = g_cntF0[w]; l = levelOf(g_cnt0[w]); }
                else        { int c = g_cnt1[w]; cf = min(c, targetOf(c)); l = levelOf(c); }
            }
            int occ = cf > 0;
            int v0 = cf;
            int v1 = (occ && l == 0) ? 1 : 0;
            int v2 = (occ && l == 1) ? 1 : 0;
            int v3 = (occ && l == 2) ? 1 : 0;
            int x0 = v0, x1 = v1, x2 = v2, x3 = v3;
            #pragma unroll
            for (int o = 1; o < 32; o <<= 1) {
                int y0 = __shfl_up_sync(~0u, x0, o);
                int y1 = __shfl_up_sync(~0u, x1, o);
                int y2 = __shfl_up_sync(~0u, x2, o);
                int y3 = __shfl_up_sync(~0u, x3, o);
                if (lane >= o) { x0 += y0; x1 += y1; x2 += y2; x3 += y3; }
            }
            if (lane == 31) { ws0[warp] = x0; ws1[warp] = x1; ws2[warp] = x2; ws3[warp] = x3; }
            __syncthreads();
            if (warp == 0) {
                int y0 = ws0[lane], y1 = ws1[lane], y2 = ws2[lane], y3 = ws3[lane];
                #pragma unroll
                for (int o = 1; o < 32; o <<= 1) {
                    int z0 = __shfl_up_sync(~0u, y0, o);
                    int z1 = __shfl_up_sync(~0u, y1, o);
                    int z2 = __shfl_up_sync(~0u, y2, o);
                    int z3 = __shfl_up_sync(~0u, y3, o);
                    if (lane >= o) { y0 += z0; y1 += z1; y2 += z2; y3 += z3; }
                }
                ws0[lane] = y0; ws1[lane] = y1; ws2[lane] = y2; ws3[lane] = y3;
            }
            __syncthreads();
            int b1 = warp ? ws1[warp - 1] : 0;
            int b2 = warp ? ws2[warp - 1] : 0;
            int b3 = warp ? ws3[warp - 1] : 0;
            if (w < WMAX) {
                lvlArr[w] = l;
                int e1 = x1 - v1 + b1 + c1;
                int e2 = x2 - v2 + b2 + c2;
                int e3 = x3 - v3 + b3 + c3;
                contArr[w] = (l == 0) ? e1 : (l == 1) ? e2 : e3;
            }
            c0 += ws0[31]; c1 += ws1[31]; c2 += ws2[31]; c3 += ws3[31];
            __syncthreads();
        }
        if (tid == 0) {
            g_nwin[3 * s + 0] = c1;
            g_nwin[3 * s + 1] = c2;
            g_nwin[3 * s + 2] = c3;
        }
        if (s == 0) M0 = c0;
        __syncthreads();
    }
    if (tid == 0) {
        g_total = M0;
        long long M = M0;
        long long o = 0;
        g_off[0] = 0;       o = M * 192;          // feats
        g_off[1] = o;       o += M * 4;           // coords
        const int T[3] = {16, 32, 48};
        for (int s = 0; s < 2; s++) {
            for (int d = 0; d < 3; d++) { g_off[2 + 6 * s + d] = o; o += (long long)g_nwin[3 * s + d] * T[d] * 192; }
            for (int d = 0; d < 3; d++) { g_off[5 + 6 * s + d] = o; o += (long long)g_nwin[3 * s + d] * T[d]; }
        }
        g_off[14] = o;
    }
}

// ---- decoupled-lookback select: kept voxels in original order -> srcOf --------
#define SEL_THREADS 256
#define SEL_ITEMS   8
#define SEL_TILE    (SEL_THREADS * SEL_ITEMS)

__global__ void k_select(int n) {
    __shared__ int s_bid;
    __shared__ int s_wsum[8];
    __shared__ int s_base;
    if (threadIdx.x == 0) s_bid = atomicAdd(&g_ticket, 1);
    __syncthreads();
    int bid = s_bid;
    int base = bid * SEL_TILE;

    int flags[SEL_ITEMS];
    int cnt = 0;
    #pragma unroll
    for (int k = 0; k < SEL_ITEMS; k++) {
        int p = base + threadIdx.x * SEL_ITEMS + k;
        int f = (p < n) ? g_keepF[p] : 0;
        flags[k] = f; cnt += f;
    }
    int lane = threadIdx.x & 31, warp = threadIdx.x >> 5;
    int x = cnt;
    #pragma unroll
    for (int o = 1; o < 32; o <<= 1) { int y = __shfl_up_sync(~0u, x, o); if (lane >= o) x += y; }
    if (lane == 31) s_wsum[warp] = x;
    __syncthreads();
    if (threadIdx.x < 8) {
        int y = s_wsum[threadIdx.x];
        #pragma unroll
        for (int o = 1; o < 8; o <<= 1) { int z = __shfl_up_sync(0xFFu, y, o); if ((int)threadIdx.x >= o) y += z; }
        s_wsum[threadIdx.x] = y;
    }
    __syncthreads();
    int blockAgg   = s_wsum[7];
    int threadExcl = x - cnt + (warp ? s_wsum[warp - 1] : 0);

    if (threadIdx.x == 0) {
        if (bid == 0) {
            atomicExch(&g_status[0], ((unsigned long long)blockAgg << 2) | 2ull);
            s_base = 0;
        } else {
            atomicExch(&g_status[bid], ((unsigned long long)blockAgg << 2) | 1ull);
            int excl = 0;
            int look = bid - 1;
            while (true) {
                unsigned long long s;
                do { s = atomicAdd(&g_status[look], 0ull); } while ((s & 3ull) == 0ull);
                excl += (int)(s >> 2);
                if ((s & 3ull) == 2ull) break;
                look--;
            }
            atomicExch(&g_status[bid], ((unsigned long long)(excl + blockAgg) << 2) | 2ull);
            s_base = excl;
        }
    }
    __syncthreads();
    int pos = s_base + threadExcl;
    #pragma unroll
    for (int k = 0; k < SEL_ITEMS; k++) {
        if (flags[k]) g_srcOf[pos++] = base + threadIdx.x * SEL_ITEMS + k;
    }
}

// ---- writers: feats gather + coords (fused) ------------------------------------
__global__ void k_feats(const float4* __restrict__ fin, const int* __restrict__ coords,
                        float* __restrict__ out) {
    int M = g_total;
    int idx = blockIdx.x * blockDim.x + threadIdx.x;
    int pos = idx / 48, c = idx - 48 * pos;
    if (pos >= M) return;
    int src = __ldg(&g_srcOf[pos]);
    float4 v = __ldcs(&fin[(long long)src * 48 + c]);
    __stcs(&((float4*)out)[(long long)pos * 48 + c], v);
    if (c == 0) {
        int4 cc = ((const int4*)coords)[src];
        float4* oc = (float4*)(out + g_off[1]);
        __stcs(&oc[pos], make_float4((float)cc.x, (float)cc.y, (float)cc.z, (float)cc.w));
    }
}

// ---- pe + mask writer: one block per (shift, window), filters its own segment --
__global__ void k_pe(float* __restrict__ out) {
    int b = blockIdx.x;
    int s = (b >= WMAX) ? 1 : 0;
    int w = b - s * WMAX;

    int cntSeg, cntF, segStart, lvl, conti;
    const int* arr;
    if (s == 0) {
        cntSeg = g_cnt0[w];
        cntF   = g_cntF0[w];
        if (cntF == 0) return;
        segStart = g_startA[w] - cntSeg;
        lvl = g_lvl0[w]; conti = g_conti0[w];
        arr = g_arrA;
    } else {
        cntSeg = g_cnt1[w];
        if (cntSeg == 0) return;
        cntF = min(cntSeg, targetOf(cntSeg));
        segStart = g_startB[w] - cntSeg;
        lvl = g_lvl1[w]; conti = g_conti1[w];
        arr = g_arrB;
        cntSeg = cntF;        // for s=1 the first cntF sorted entries are the kept set
    }
    int T = tokensOf(lvl);
    long long pebase   = g_off[2 + 6 * s + lvl] + (long long)conti * T * 192;
    long long maskbase = g_off[5 + 6 * s + lvl] + (long long)conti * T;

    __shared__ int rowtab[48];
    int t = threadIdx.x;
    if (t < 32) {
        int lane = t;
        int nk = 0;
        for (int base = 0; base < cntSeg; base += 32) {
            int r = base + lane;
            int v = (r < cntSeg) ? arr[segStart + r] : -1;
            int f = (v >= 0) ? ((s == 0) ? g_keepF[v] : 1) : 0;
            unsigned m = __ballot_sync(~0u, f);
            if (f) {
                int slot = nk + __popc(m & ((1u << lane) - 1));
                int tb = g_tb[v];
                rowtab[slot] = s ? (tb >> 16) : (tb & 0xFFFF);
            }
            nk += __popc(m);
        }
        // pad
        for (int p = nk + lane; p < T; p += 32) rowtab[p] = -1;
    }
    if (t < T) __stcs(&out[maskbase + t], (t >= cntF) ? 1.0f : 0.0f);
    __syncthreads();

    const float4* tab4 = (const float4*)g_tab;
    float4* o4 = (float4*)(out + pebase);
    int tot4 = T * 48;
    for (int j = t; j < tot4; j += blockDim.x) {
        int tt = j / 48, f4 = j - 48 * tt;
        int tb = rowtab[tt];
        float4 v = (tb >= 0) ? __ldg(&tab4[tb * 48 + f4]) : make_float4(0.f, 0.f, 0.f, 0.f);
        __stcs(&o4[j], v);
    }
}

// ---------------------------------------------------------------------------
extern "C" void kernel_launch(void* const* d_in, const int* in_sizes, int n_in,
                              void* d_out, int out_size) {
    const float* feats  = (const float*)d_in[0];
    const int*   coords = (const int*)d_in[1];
    float* out = (float*)d_out;

    int n = in_sizes[1] / 4;
    if (n > NV) n = NV;
    if (n <= 0) return;
    int nb = (n + 255) / 256;
    int wb = (WMAX + 7) / 8;     // 8 warps / block for per-window kernels

    // device addresses of the __device__ symbols (host-side symbol decay is NOT
    // a valid device pointer — this was the R6 bug)
    void *p_cnt0, *p_cnt1, *p_stA, *p_stB;
    cudaGetSymbolAddress(&p_cnt0, g_cnt0);
    cudaGetSymbolAddress(&p_cnt1, g_cnt1);
    cudaGetSymbolAddress(&p_stA,  g_startA);
    cudaGetSymbolAddress(&p_stB,  g_startB);

    k_tab<<<(400 * 192 + 255) / 256, 256>>>();     // LUT + zero counters/status
    k_wins<<<nb, 256>>>(coords, n);
    k_exscan<<<1, 1024>>>((const int*)p_cnt0, (int*)p_stA);
    k_scat0<<<nb, 256>>>(n);
    k_sw0<<<wb, 256>>>();
    k_exscan<<<1, 1024>>>((const int*)p_cnt1, (int*)p_stB);
    k_scat1<<<nb, 256>>>(n);
    k_sw1<<<wb, 256>>>();
    k_meta<<<1, 1024>>>();

    int selblk = (n + SEL_TILE - 1) / SEL_TILE;
    k_select<<<selblk, SEL_THREADS>>>(n);

    k_feats<<<(n * 48 + 255) / 256, 256>>>((const float4*)feats, coords, out);
    k_pe<<<2 * WMAX, 256>>>(out);
}

// round 9
// speedup vs baseline: 1.7768x; 1.1453x over previous
#include <cuda_runtime.h>

// ---------------------------------------------------------------------------
// SparseWindowPartitionLayer — full GPU pipeline, graph-capturable, no CUB.
//   win id < 16810; T=16/32/48 by pre-drop window count; FEAT_DIM=192
//   pe depends only on in-window coords => 400-row LUT (L2 resident)
//   Stable per-window order = atomic scatter into histogrammed segments,
//   then per-window warp bitonic sort by original voxel index.
//   Drops are rare => all keep/count bookkeeping is subtract-on-drop.
// ---------------------------------------------------------------------------

#define NV    300000
#define WMAX  16810

__device__ int  g_W0[NV], g_W1[NV], g_tb[NV];   // tb0 | tb1<<16
__device__ int  g_arrA[NV], g_arrB[NV];         // window-grouped voxel ids
__device__ int  g_keep0[NV], g_keepF[NV], g_srcOf[NV];
__device__ int  g_cnt0[WMAX], g_cnt1[WMAX], g_cntF0[WMAX];
__device__ int  g_startA[WMAX], g_startB[WMAX]; // excl-scan, bumped to seg end
__device__ int  g_lvl0[WMAX], g_lvl1[WMAX], g_conti0[WMAX], g_conti1[WMAX];
__device__ int  g_nwin[6], g_total, g_done;
__device__ long long g_off[16];
__device__ float g_tab[400 * 192];
__device__ unsigned long long g_status[256];
__device__ int  g_ticket;

__device__ __forceinline__ int targetOf(int c) { return c < 16 ? 16 : (c < 32 ? 32 : 48); }
__device__ __forceinline__ int levelOf(int c)  { return c < 16 ? 0  : (c < 32 ? 1  : 2);  }
__device__ __forceinline__ int tokensOf(int l) { return l == 2 ? 48 : (16 << l); }

// ---- pe LUT + zero counters/status + default keep flags ----------------------
__global__ void k_tab(int n) {
    int t = blockIdx.x * blockDim.x + threadIdx.x;
    if (t < WMAX) { g_cnt0[t] = 0; g_cnt1[t] = 0; g_cntF0[t] = 0; }
    if (t < 256)  g_status[t] = 0ull;
    if (t == 0)   { g_ticket = 0; g_done = 0; }
    if (t < n)    { g_keep0[t] = 1; g_keepF[t] = 1; }
    if (t >= 400 * 192) return;
    int row = t / 192, f = t - 192 * row;
    int cx = row % 10, cy = (row / 10) % 10, cz = row / 100;
    int axis = f / 64, k = f - 64 * axis;
    int j = k >> 1, ph = k & 1;
    float v = (axis == 0) ? (float)(cx - 5)
            : (axis == 1) ? (float)(cy - 5)
                          : (float)(cz - 2);
    float invf = (float)exp(log(1000.0) * (double)j / 32.0);
    float e = v / invf;
    g_tab[t] = ph ? cosf(e) : sinf(e);
}

// ---- window ids + BOTH histograms (cnt1 speculative) + pe row ids -------------
__global__ void k_wins(const int* __restrict__ coords, int n) {
    int i = blockIdx.x * blockDim.x + threadIdx.x;
    if (i >= n) return;
    int4 c = ((const int4*)coords)[i];      // (b, z, y, x)
    int b = c.x, z = c.y, y = c.z, x = c.w;
    int w0 = b * 8405 + ((x + 10) / 10) * 205 + ((y + 10) / 10) * 5 + ((z + 4) / 4);
    int w1 = b * 8405 + ((x + 5)  / 10) * 205 + ((y + 5)  / 10) * 5 + ((z + 2) / 4);
    g_W0[i] = w0;
    g_W1[i] = w1;
    int tb0 = ((z % 4) * 10 + (y % 10)) * 10 + (x % 10);
    int tb1 = (((z + 2) % 4) * 10 + ((y + 5) % 10)) * 10 + ((x + 5) % 10);
    g_tb[i] = tb0 | (tb1 << 16);
    atomicAdd(&g_cnt0[w0], 1);
    atomicAdd(&g_cnt1[w1], 1);   // speculative; sw0 subtracts rare drops
}

// ---- single-block exclusive scan over WMAX counters (+optional copy) ----------
__global__ void k_exscan(const int* __restrict__ in, int* __restrict__ out,
                         int* __restrict__ cpy) {
    __shared__ int ws[32];
    int tid = threadIdx.x, lane = tid & 31, warp = tid >> 5;
    int carry = 0;
    for (int base = 0; base < WMAX; base += 1024) {
        int w = base + tid;
        int v = (w < WMAX) ? in[w] : 0;
        if (cpy && w < WMAX) cpy[w] = v;
        int x = v;
        #pragma unroll
        for (int o = 1; o < 32; o <<= 1) { int y = __shfl_up_sync(~0u, x, o); if (lane >= o) x += y; }
        if (lane == 31) ws[warp] = x;
        __syncthreads();
        if (warp == 0) {
            int y = ws[lane];
            #pragma unroll
            for (int o = 1; o < 32; o <<= 1) { int z = __shfl_up_sync(~0u, y, o); if (lane >= o) y += z; }
            ws[lane] = y;
        }
        __syncthreads();
        int excl = x - v + (warp ? ws[warp - 1] : 0) + carry;
        if (w < WMAX) out[w] = excl;
        carry += ws[31];
        __syncthreads();
    }
}

// ---- scatter voxels into window segments --------------------------------------
__global__ void k_scat0(int n) {
    int i = blockIdx.x * blockDim.x + threadIdx.x;
    if (i >= n) return;
    int pos = atomicAdd(&g_startA[g_W0[i]], 1);
    g_arrA[pos] = i;
}

__global__ void k_scat1(int n) {
    int i = blockIdx.x * blockDim.x + threadIdx.x;
    if (i >= n) return;
    if (!g_keep0[i]) return;
    int pos = atomicAdd(&g_startB[g_W1[i]], 1);
    g_arrB[pos] = i;
}

// ---- register bitonic sort over 32*R elements ----------------------------------
template <int R>
__device__ __forceinline__ void bitonicReg(int (&v)[R], int lane) {
    const int NE = 32 * R;
    #pragma unroll
    for (int k = 2; k <= NE; k <<= 1) {
        #pragma unroll
        for (int j = k >> 1; j > 0; j >>= 1) {
            if (j >= 32) {
                int s = j >> 5;
                #pragma unroll
                for (int r = 0; r < R; r++) {
                    int pr = r ^ s;
                    if (r < pr) {
                        bool up = (((lane + 32 * r) & k) == 0);
                        int x = v[r], y = v[pr];
                        int lo = min(x, y), hi = max(x, y);
                        v[r]  = up ? lo : hi;
                        v[pr] = up ? hi : lo;
                    }
                }
            } else {
                #pragma unroll
                for (int r = 0; r < R; r++) {
                    int e = lane + 32 * r;
                    bool up = ((e & k) == 0);
                    int o = __shfl_xor_sync(~0u, v[r], j);
                    bool lower = ((lane & j) == 0);
                    int mn = min(v[r], o), mx = max(v[r], o);
                    v[r] = (up == lower) ? mn : mx;
                }
            }
        }
    }
}

template <int R>
__device__ __forceinline__ void sortReg(int* a, int cnt, int lane) {
    int v[R];
    #pragma unroll
    for (int r = 0; r < R; r++) {
        int e = lane + 32 * r;
        v[r] = (e < cnt) ? a[e] : 0x7FFFFFFF;
    }
    bitonicReg<R>(v, lane);
    #pragma unroll
    for (int r = 0; r < R; r++) {
        int e = lane + 32 * r;
        if (e < cnt) a[e] = v[r];
    }
}

__device__ void sortSeg(int* a, int cnt, int lane) {
    if (cnt <= 32)       sortReg<1>(a, cnt, lane);
    else if (cnt <= 64)  sortReg<2>(a, cnt, lane);
    else if (cnt <= 128) sortReg<4>(a, cnt, lane);
    else {
        // robust fallback (not expected for this dataset): odd-even transposition
        for (int pass = 0; pass < cnt; pass++) {
            for (int p = (pass & 1) + 2 * lane; p + 1 < cnt; p += 64) {
                int x = a[p], y = a[p + 1];
                if (x > y) { a[p] = y; a[p + 1] = x; }
            }
            __syncwarp();
            __threadfence_block();
        }
    }
    __syncwarp();
}

// ---- per-window sorts; bookkeeping only for (rare) drops -----------------------
__global__ void k_sw0() {
    int wid = blockIdx.x * (blockDim.x >> 5) + (threadIdx.x >> 5);
    if (wid >= WMAX) return;
    int lane = threadIdx.x & 31;
    int cnt = g_cnt0[wid];
    if (cnt == 0) return;
    int seg = g_startA[wid] - cnt;
    sortSeg(g_arrA + seg, cnt, lane);
    int t = targetOf(cnt);
    for (int e = t + lane; e < cnt; e += 32) {   // drops only
        int v = g_arrA[seg + e];
        g_keep0[v] = 0;
        g_keepF[v] = 0;
        atomicSub(&g_cnt1[g_W1[v]], 1);
        atomicSub(&g_cntF0[wid], 1);
    }
}

__global__ void k_sw1() {
    int wid = blockIdx.x * (blockDim.x >> 5) + (threadIdx.x >> 5);
    if (wid >= WMAX) return;
    int lane = threadIdx.x & 31;
    int cnt = g_cnt1[wid];                       // exact kept0 count
    if (cnt == 0) return;
    int seg = g_startB[wid] - cnt;
    sortSeg(g_arrB + seg, cnt, lane);
    int t = targetOf(cnt);
    for (int e = t + lane; e < cnt; e += 32) {   // drops only
        int v = g_arrB[seg + e];
        g_keepF[v] = 0;
        atomicSub(&g_cntF0[g_W0[v]], 1);
    }
}

// ---- meta body (one block per shift): lvl/conti, nwin, total, offsets ----------
__device__ void meta_body(int s) {
    __shared__ int sh0[8], sh1[8], sh2[8], sh3[8];
    int tid = threadIdx.x, lane = tid & 31, warp = tid >> 5;
    int* lvlArr  = s ? g_lvl1   : g_lvl0;
    int* contArr = s ? g_conti1 : g_conti0;
    int c0 = 0, c1 = 0, c2 = 0, c3 = 0;
    for (int base = 0; base < WMAX; base += 1024) {
        int cf[4], lv[4], f1[4], f2[4], f3[4];
        #pragma unroll
        for (int k = 0; k < 4; k++) {
            int w = base + tid * 4 + k;
            cf[k] = 0; lv[k] = 0;
            if (w < WMAX) {
                if (s == 0) { cf[k] = g_cntF0[w]; lv[k] = levelOf(g_cnt0[w]); }
                else        { int c = g_cnt1[w]; cf[k] = min(c, targetOf(c)); lv[k] = levelOf(c); }
            }
            int occ = cf[k] > 0;
            f1[k] = (occ && lv[k] == 0) ? 1 : 0;
            f2[k] = (occ && lv[k] == 1) ? 1 : 0;
            f3[k] = (occ && lv[k] == 2) ? 1 : 0;
        }
        int t0 = cf[0] + cf[1] + cf[2] + cf[3];
        int t1 = f1[0] + f1[1] + f1[2] + f1[3];
        int t2 = f2[0] + f2[1] + f2[2] + f2[3];
        int t3 = f3[0] + f3[1] + f3[2] + f3[3];
        int x0 = t0, x1 = t1, x2 = t2, x3 = t3;
        #pragma unroll
        for (int o = 1; o < 32; o <<= 1) {
            int y0 = __shfl_up_sync(~0u, x0, o);
            int y1 = __shfl_up_sync(~0u, x1, o);
            int y2 = __shfl_up_sync(~0u, x2, o);
            int y3 = __shfl_up_sync(~0u, x3, o);
            if (lane >= o) { x0 += y0; x1 += y1; x2 += y2; x3 += y3; }
        }
        if (lane == 31) { sh0[warp] = x0; sh1[warp] = x1; sh2[warp] = x2; sh3[warp] = x3; }
        __syncthreads();
        if (tid < 8) {
            int y0 = sh0[tid], y1 = sh1[tid], y2 = sh2[tid], y3 = sh3[tid];
            #pragma unroll
            for (int o = 1; o < 8; o <<= 1) {
                int z0 = __shfl_up_sync(0xFFu, y0, o);
                int z1 = __shfl_up_sync(0xFFu, y1, o);
                int z2 = __shfl_up_sync(0xFFu, y2, o);
                int z3 = __shfl_up_sync(0xFFu, y3, o);
                if (tid >= o) { y0 += z0; y1 += z1; y2 += z2; y3 += z3; }
            }
            sh0[tid] = y0; sh1[tid] = y1; sh2[tid] = y2; sh3[tid] = y3;
        }
        __syncthreads();
        int b1 = x1 - t1 + (warp ? sh1[warp - 1] : 0) + c1;
        int b2 = x2 - t2 + (warp ? sh2[warp - 1] : 0) + c2;
        int b3 = x3 - t3 + (warp ? sh3[warp - 1] : 0) + c3;
        #pragma unroll
        for (int k = 0; k < 4; k++) {
            int w = base + tid * 4 + k;
            if (w < WMAX) {
                lvlArr[w]  = lv[k];
                contArr[w] = (lv[k] == 0) ? b1 : (lv[k] == 1) ? b2 : b3;
            }
            b1 += f1[k]; b2 += f2[k]; b3 += f3[k];
        }
        c0 += sh0[7]; c1 += sh1[7]; c2 += sh2[7]; c3 += sh3[7];
        __syncthreads();
    }
    if (tid == 0) {
        g_nwin[3 * s + 0] = c1;
        g_nwin[3 * s + 1] = c2;
        g_nwin[3 * s + 2] = c3;
        if (s == 0) g_total = c0;
        __threadfence();
        int prev = atomicAdd(&g_done, 1);
        if (prev == 1) {                       // second finisher computes offsets
            __threadfence();
            long long M = *((volatile int*)&g_total);
            int nw[6];
            #pragma unroll
            for (int q = 0; q < 6; q++) nw[q] = *((volatile int*)&g_nwin[q]);
            long long o = 0;
            g_off[0] = 0;       o = M * 192;          // feats
            g_off[1] = o;       o += M * 4;           // coords
            const int T[3] = {16, 32, 48};
            for (int ss = 0; ss < 2; ss++) {
                for (int d = 0; d < 3; d++) { g_off[2 + 6 * ss + d] = o; o += (long long)nw[3 * ss + d] * T[d] * 192; }
                for (int d = 0; d < 3; d++) { g_off[5 + 6 * ss + d] = o; o += (long long)nw[3 * ss + d] * T[d]; }
            }
            g_off[14] = o;
        }
    }
}

// ---- select body: decoupled-lookback compaction of keepF -> srcOf --------------
#define SEL_THREADS 256
#define SEL_ITEMS   8
#define SEL_TILE    (SEL_THREADS * SEL_ITEMS)

__device__ void select_body(int n) {
    __shared__ int s_bid;
    __shared__ int s_wsum[8];
    __shared__ int s_base;
    if (threadIdx.x == 0) s_bid = atomicAdd(&g_ticket, 1);
    __syncthreads();
    int bid = s_bid;
    int base = bid * SEL_TILE;

    int flags[SEL_ITEMS];
    int cnt = 0;
    #pragma unroll
    for (int k = 0; k < SEL_ITEMS; k++) {
        int p = base + threadIdx.x * SEL_ITEMS + k;
        int f = (p < n) ? g_keepF[p] : 0;
        flags[k] = f; cnt += f;
    }
    int lane = threadIdx.x & 31, warp = threadIdx.x >> 5;
    int x = cnt;
    #pragma unroll
    for (int o = 1; o < 32; o <<= 1) { int y = __shfl_up_sync(~0u, x, o); if (lane >= o) x += y; }
    if (lane == 31) s_wsum[warp] = x;
    __syncthreads();
    if (threadIdx.x < 8) {
        int y = s_wsum[threadIdx.x];
        #pragma unroll
        for (int o = 1; o < 8; o <<= 1) { int z = __shfl_up_sync(0xFFu, y, o); if ((int)threadIdx.x >= o) y += z; }
        s_wsum[threadIdx.x] = y;
    }
    __syncthreads();
    int blockAgg   = s_wsum[7];
    int threadExcl = x - cnt + (warp ? s_wsum[warp - 1] : 0);

    if (threadIdx.x == 0) {
        if (bid == 0) {
            atomicExch(&g_status[0], ((unsigned long long)blockAgg << 2) | 2ull);
            s_base = 0;
        } else {
            atomicExch(&g_status[bid], ((unsigned long long)blockAgg << 2) | 1ull);
            int excl = 0;
            int look = bid - 1;
            while (true) {
                unsigned long long s;
                do { s = atomicAdd(&g_status[look], 0ull); } while ((s & 3ull) == 0ull);
                excl += (int)(s >> 2);
                if ((s & 3ull) == 2ull) break;
                look--;
            }
            atomicExch(&g_status[bid], ((unsigned long long)(excl + blockAgg) << 2) | 2ull);
            s_base = excl;
        }
    }
    __syncthreads();
    int pos = s_base + threadExcl;
    #pragma unroll
    for (int k = 0; k < SEL_ITEMS; k++) {
        if (flags[k]) g_srcOf[pos++] = base + threadIdx.x * SEL_ITEMS + k;
    }
}

// ---- fused meta (last 2 blocks) + select (rest) ---------------------------------
__global__ void k_metasel(int n) {
    if ((int)blockIdx.x >= (int)gridDim.x - 2) {
        meta_body((int)blockIdx.x - ((int)gridDim.x - 2));
        return;
    }
    select_body(n);
}

// ---- fused writer: feats+coords gather (first featBlocks) then pe+mask ----------
__global__ void k_write(const float4* __restrict__ fin, const int* __restrict__ coords,
                        float* __restrict__ out, int featBlocks) {
    if ((int)blockIdx.x < featBlocks) {
        int M = g_total;
        int idx = blockIdx.x * blockDim.x + threadIdx.x;
        int pos = idx / 48, c = idx - 48 * pos;
        if (pos >= M) return;
        int src = __ldg(&g_srcOf[pos]);
        float4 v = __ldcs(&fin[(long long)src * 48 + c]);
        __stcs(&((float4*)out)[(long long)pos * 48 + c], v);
        if (c == 0) {
            int4 cc = ((const int4*)coords)[src];
            float4* oc = (float4*)(out + g_off[1]);
            __stcs(&oc[pos], make_float4((float)cc.x, (float)cc.y, (float)cc.z, (float)cc.w));
        }
        return;
    }

    int b = (int)blockIdx.x - featBlocks;      // [0, 2*WMAX)
    int s = (b >= WMAX) ? 1 : 0;
    int w = b - s * WMAX;

    int cntSeg, cntF, segStart, lvl, conti;
    const int* arr;
    if (s == 0) {
        cntSeg = g_cnt0[w];
        cntF   = g_cntF0[w];
        if (cntF == 0) return;
        segStart = g_startA[w] - cntSeg;
        lvl = g_lvl0[w]; conti = g_conti0[w];
        arr = g_arrA;
    } else {
        cntSeg = g_cnt1[w];
        if (cntSeg == 0) return;
        cntF = min(cntSeg, targetOf(cntSeg));
        segStart = g_startB[w] - cntSeg;
        lvl = g_lvl1[w]; conti = g_conti1[w];
        arr = g_arrB;
        cntSeg = cntF;        // first cntF sorted entries are the kept set
    }
    int T = tokensOf(lvl);
    long long pebase   = g_off[2 + 6 * s + lvl] + (long long)conti * T * 192;
    long long maskbase = g_off[5 + 6 * s + lvl] + (long long)conti * T;

    __shared__ int rowtab[48];
    int t = threadIdx.x;
    if (t < 32) {
        int lane = t;
        int nk = 0;
        for (int base = 0; base < cntSeg; base += 32) {
            int r = base + lane;
            int v = (r < cntSeg) ? arr[segStart + r] : -1;
            int f = (v >= 0) ? ((s == 0) ? g_keepF[v] : 1) : 0;
            unsigned m = __ballot_sync(~0u, f);
            if (f) {
                int slot = nk + __popc(m & ((1u << lane) - 1));
                int tb = g_tb[v];
                rowtab[slot] = s ? (tb >> 16) : (tb & 0xFFFF);
            }
            nk += __popc(m);
        }
        for (int p = nk + lane; p < T; p += 32) rowtab[p] = -1;
    }
    if (t < T) __stcs(&out[maskbase + t], (t >= cntF) ? 1.0f : 0.0f);
    __syncthreads();

    const float4* tab4 = (const float4*)g_tab;
    float4* o4 = (float4*)(out + pebase);
    int tot4 = T * 48;
    for (int j = t; j < tot4; j += blockDim.x) {
        int tt = j / 48, f4 = j - 48 * tt;
        int tb = rowtab[tt];
        float4 v = (tb >= 0) ? __ldg(&tab4[tb * 48 + f4]) : make_float4(0.f, 0.f, 0.f, 0.f);
        __stcs(&o4[j], v);
    }
}

// ---------------------------------------------------------------------------
extern "C" void kernel_launch(void* const* d_in, const int* in_sizes, int n_in,
                              void* d_out, int out_size) {
    const float* feats  = (const float*)d_in[0];
    const int*   coords = (const int*)d_in[1];
    float* out = (float*)d_out;

    int n = in_sizes[1] / 4;
    if (n > NV) n = NV;
    if (n <= 0) return;
    int nb = (n + 255) / 256;
    int wb = (WMAX + 7) / 8;     // 8 warps / block for per-window sort kernels

    // device addresses of __device__ symbols (host-side decay is NOT a device ptr)
    void *p_cnt0, *p_cnt1, *p_cntF0, *p_stA, *p_stB;
    cudaGetSymbolAddress(&p_cnt0,  g_cnt0);
    cudaGetSymbolAddress(&p_cnt1,  g_cnt1);
    cudaGetSymbolAddress(&p_cntF0, g_cntF0);
    cudaGetSymbolAddress(&p_stA,   g_startA);
    cudaGetSymbolAddress(&p_stB,   g_startB);

    int tabBlocks = max(nb, (400 * 192 + 255) / 256);

    k_tab<<<tabBlocks, 256>>>(n);                 // LUT + zero + keep defaults
    k_wins<<<nb, 256>>>(coords, n);
    k_exscan<<<1, 1024>>>((const int*)p_cnt0, (int*)p_stA, (int*)p_cntF0);
    k_scat0<<<nb, 256>>>(n);
    k_sw0<<<wb, 256>>>();
    k_exscan<<<1, 1024>>>((const int*)p_cnt1, (int*)p_stB, nullptr);
    k_scat1<<<nb, 256>>>(n);
    k_sw1<<<wb, 256>>>();

    int selblk = (n + SEL_TILE - 1) / SEL_TILE;
    k_metasel<<<selblk + 2, SEL_THREADS>>>(n);

    int featBlocks = (n * 48 + 255) / 256;
    k_write<<<featBlocks + 2 * WMAX, 256>>>((const float4*)feats, coords, out, featBlocks);
}

// round 10
// speedup vs baseline: 1.8947x; 1.0664x over previous
#include <cuda_runtime.h>

// ---------------------------------------------------------------------------
// SparseWindowPartitionLayer — full GPU pipeline, graph-capturable, no CUB.
//   win id < 16810; T=16/32/48 by pre-drop window count; FEAT_DIM=192
//   pe depends only on in-window coords => 400-row LUT (L2 resident)
//   Stable per-window order: rank-from-histogram scatter (NO scatter atomics),
//   then per-window warp bitonic sort by original voxel index.
//   Drops are rare => keep/count bookkeeping is subtract-on-drop; dropped
//   voxels' shift-1 slots get INT_MAX sentinels that sort to the segment tail.
// ---------------------------------------------------------------------------

#define NV    300000
#define WMAX  16810

__device__ int  g_W0[NV], g_W1[NV], g_tb[NV];   // tb0 | tb1<<16
__device__ int2 g_rank[NV];                     // (rank in w0, rank in w1-spec)
__device__ int  g_arrA[NV], g_arrB[NV];         // window-grouped voxel ids
__device__ int  g_keepF[NV], g_srcOf[NV];
__device__ int  g_cnt0[WMAX], g_cnt1[WMAX];     // cnt1 = speculative (pre-drop)
__device__ int  g_cnt1c[WMAX], g_cntF0[WMAX];   // corrected counts
__device__ int  g_startA[WMAX], g_startB[WMAX]; // pure exclusive scans
__device__ int  g_lvl0[WMAX], g_lvl1[WMAX], g_conti0[WMAX], g_conti1[WMAX];
__device__ int  g_nwin[6], g_total, g_done;
__device__ long long g_off[16];
__device__ float g_tab[400 * 192];
__device__ unsigned long long g_status[256];
__device__ int  g_ticket;

__device__ __forceinline__ int targetOf(int c) { return c < 16 ? 16 : (c < 32 ? 32 : 48); }
__device__ __forceinline__ int levelOf(int c)  { return c < 16 ? 0  : (c < 32 ? 1  : 2);  }
__device__ __forceinline__ int tokensOf(int l) { return l == 2 ? 48 : (16 << l); }

// ---- pe LUT + zero counters/status + default keepF ----------------------------
__global__ void k_tab(int n) {
    int t = blockIdx.x * blockDim.x + threadIdx.x;
    if (t < WMAX) { g_cnt0[t] = 0; g_cnt1[t] = 0; }
    if (t < 256)  g_status[t] = 0ull;
    if (t == 0)   { g_ticket = 0; g_done = 0; }
    if (t < n)    g_keepF[t] = 1;
    if (t >= 400 * 192) return;
    int row = t / 192, f = t - 192 * row;
    int cx = row % 10, cy = (row / 10) % 10, cz = row / 100;
    int axis = f / 64, k = f - 64 * axis;
    int j = k >> 1, ph = k & 1;
    float v = (axis == 0) ? (float)(cx - 5)
            : (axis == 1) ? (float)(cy - 5)
                          : (float)(cz - 2);
    float invf = (float)exp(log(1000.0) * (double)j / 32.0);
    float e = v / invf;
    g_tab[t] = ph ? cosf(e) : sinf(e);
}

// ---- window ids + both histograms + per-voxel ranks + pe row ids --------------
__global__ void k_wins(const int* __restrict__ coords, int n) {
    int i = blockIdx.x * blockDim.x + threadIdx.x;
    if (i >= n) return;
    int4 c = ((const int4*)coords)[i];      // (b, z, y, x)
    int b = c.x, z = c.y, y = c.z, x = c.w;
    int w0 = b * 8405 + ((x + 10) / 10) * 205 + ((y + 10) / 10) * 5 + ((z + 4) / 4);
    int w1 = b * 8405 + ((x + 5)  / 10) * 205 + ((y + 5)  / 10) * 5 + ((z + 2) / 4);
    g_W0[i] = w0;
    g_W1[i] = w1;
    int tb0 = ((z % 4) * 10 + (y % 10)) * 10 + (x % 10);
    int tb1 = (((z + 2) % 4) * 10 + ((y + 5) % 10)) * 10 + ((x + 5) % 10);
    g_tb[i] = tb0 | (tb1 << 16);
    int r0 = atomicAdd(&g_cnt0[w0], 1);
    int r1 = atomicAdd(&g_cnt1[w1], 1);     // speculative rank (pre-drop)
    g_rank[i] = make_int2(r0, r1);
}

// ---- one launch, two blocks: scan cnt0->startA (copy cntF0), cnt1->startB ------
__device__ void exscan_body(const int* __restrict__ in, int* __restrict__ out,
                            int* __restrict__ cpy) {
    __shared__ int ws[32];
    int tid = threadIdx.x, lane = tid & 31, warp = tid >> 5;
    int carry = 0;
    for (int base = 0; base < WMAX; base += 1024) {
        int w = base + tid;
        int v = (w < WMAX) ? in[w] : 0;
        if (w < WMAX) cpy[w] = v;
        int x = v;
        #pragma unroll
        for (int o = 1; o < 32; o <<= 1) { int y = __shfl_up_sync(~0u, x, o); if (lane >= o) x += y; }
        if (lane == 31) ws[warp] = x;
        __syncthreads();
        if (warp == 0) {
            int y = ws[lane];
            #pragma unroll
            for (int o = 1; o < 32; o <<= 1) { int z = __shfl_up_sync(~0u, y, o); if (lane >= o) y += z; }
            ws[lane] = y;
        }
        __syncthreads();
        int excl = x - v + (warp ? ws[warp - 1] : 0) + carry;
        if (w < WMAX) out[w] = excl;
        carry += ws[31];
        __syncthreads();
    }
}

__global__ void k_exscan2() {
    if (blockIdx.x == 0) exscan_body(g_cnt0, g_startA, g_cntF0);
    else                 exscan_body(g_cnt1, g_startB, g_cnt1c);
}

// ---- atomic-free scatter into both segment arrays -------------------------------
__global__ void k_scat(int n) {
    int i = blockIdx.x * blockDim.x + threadIdx.x;
    if (i >= n) return;
    int2 r = g_rank[i];
    g_arrA[g_startA[g_W0[i]] + r.x] = i;
    g_arrB[g_startB[g_W1[i]] + r.y] = i;
}

// ---- register bitonic sort over 32*R elements ------------------------------------
template <int R>
__device__ __forceinline__ void bitonicReg(int (&v)[R], int lane) {
    const int NE = 32 * R;
    #pragma unroll
    for (int k = 2; k <= NE; k <<= 1) {
        #pragma unroll
        for (int j = k >> 1; j > 0; j >>= 1) {
            if (j >= 32) {
                int s = j >> 5;
                #pragma unroll
                for (int r = 0; r < R; r++) {
                    int pr = r ^ s;
                    if (r < pr) {
                        bool up = (((lane + 32 * r) & k) == 0);
                        int x = v[r], y = v[pr];
                        int lo = min(x, y), hi = max(x, y);
                        v[r]  = up ? lo : hi;
                        v[pr] = up ? hi : lo;
                    }
                }
            } else {
                #pragma unroll
                for (int r = 0; r < R; r++) {
                    int e = lane + 32 * r;
                    bool up = ((e & k) == 0);
                    int o = __shfl_xor_sync(~0u, v[r], j);
                    bool lower = ((lane & j) == 0);
                    int mn = min(v[r], o), mx = max(v[r], o);
                    v[r] = (up == lower) ? mn : mx;
                }
            }
        }
    }
}

template <int R>
__device__ __forceinline__ void sortReg(int* a, int cnt, int lane) {
    int v[R];
    #pragma unroll
    for (int r = 0; r < R; r++) {
        int e = lane + 32 * r;
        v[r] = (e < cnt) ? a[e] : 0x7FFFFFFF;
    }
    bitonicReg<R>(v, lane);
    #pragma unroll
    for (int r = 0; r < R; r++) {
        int e = lane + 32 * r;
        if (e < cnt) a[e] = v[r];
    }
}

__device__ void sortSeg(int* a, int cnt, int lane) {
    if (cnt <= 32)       sortReg<1>(a, cnt, lane);
    else if (cnt <= 64)  sortReg<2>(a, cnt, lane);
    else if (cnt <= 128) sortReg<4>(a, cnt, lane);
    else {
        // robust fallback (not expected for this dataset): odd-even transposition
        for (int pass = 0; pass < cnt; pass++) {
            for (int p = (pass & 1) + 2 * lane; p + 1 < cnt; p += 64) {
                int x = a[p], y = a[p + 1];
                if (x > y) { a[p] = y; a[p + 1] = x; }
            }
            __syncwarp();
            __threadfence_block();
        }
    }
    __syncwarp();
}

// ---- shift-0 sort; drops: flag, fix counts, sentinel the arrB slot ---------------
__global__ void k_sw0() {
    int wid = blockIdx.x * (blockDim.x >> 5) + (threadIdx.x >> 5);
    if (wid >= WMAX) return;
    int lane = threadIdx.x & 31;
    int cnt = g_cnt0[wid];
    if (cnt == 0) return;
    int seg = g_startA[wid];
    sortSeg(g_arrA + seg, cnt, lane);
    int t = targetOf(cnt);
    for (int e = t + lane; e < cnt; e += 32) {   // drops only (rare)
        int v = g_arrA[seg + e];
        g_keepF[v] = 0;
        atomicSub(&g_cnt1c[g_W1[v]], 1);
        atomicSub(&g_cntF0[wid], 1);
        g_arrB[g_startB[g_W1[v]] + g_rank[v].y] = 0x7FFFFFFF;  // sentinel
    }
}

// ---- shift-1 sort (sentinels go to tail); drops among first cnt1c entries --------
__global__ void k_sw1() {
    int wid = blockIdx.x * (blockDim.x >> 5) + (threadIdx.x >> 5);
    if (wid >= WMAX) return;
    int lane = threadIdx.x & 31;
    int spec = g_cnt1[wid];
    if (spec == 0) return;
    int seg = g_startB[wid];
    sortSeg(g_arrB + seg, spec, lane);
    int cnt = g_cnt1c[wid];                      // exact kept0 count
    int t = targetOf(cnt);
    for (int e = t + lane; e < cnt; e += 32) {   // drops only (rare)
        int v = g_arrB[seg + e];
        g_keepF[v] = 0;
        atomicSub(&g_cntF0[g_W0[v]], 1);
    }
}

// ---- meta body (one block per shift): lvl/conti, nwin, total, offsets ------------
__device__ void meta_body(int s) {
    __shared__ int sh0[8], sh1[8], sh2[8], sh3[8];
    int tid = threadIdx.x, lane = tid & 31, warp = tid >> 5;
    int* lvlArr  = s ? g_lvl1   : g_lvl0;
    int* contArr = s ? g_conti1 : g_conti0;
    int c0 = 0, c1 = 0, c2 = 0, c3 = 0;
    for (int base = 0; base < WMAX; base += 1024) {
        int cf[4], lv[4], f1[4], f2[4], f3[4];
        #pragma unroll
        for (int k = 0; k < 4; k++) {
            int w = base + tid * 4 + k;
            cf[k] = 0; lv[k] = 0;
            if (w < WMAX) {
                if (s == 0) { cf[k] = g_cntF0[w]; lv[k] = levelOf(g_cnt0[w]); }
                else        { int c = g_cnt1c[w]; cf[k] = min(c, targetOf(c)); lv[k] = levelOf(c); }
            }
            int occ = cf[k] > 0;
            f1[k] = (occ && lv[k] == 0) ? 1 : 0;
            f2[k] = (occ && lv[k] == 1) ? 1 : 0;
            f3[k] = (occ && lv[k] == 2) ? 1 : 0;
        }
        int t0 = cf[0] + cf[1] + cf[2] + cf[3];
        int t1 = f1[0] + f1[1] + f1[2] + f1[3];
        int t2 = f2[0] + f2[1] + f2[2] + f2[3];
        int t3 = f3[0] + f3[1] + f3[2] + f3[3];
        int x0 = t0, x1 = t1, x2 = t2, x3 = t3;
        #pragma unroll
        for (int o = 1; o < 32; o <<= 1) {
            int y0 = __shfl_up_sync(~0u, x0, o);
            int y1 = __shfl_up_sync(~0u, x1, o);
            int y2 = __shfl_up_sync(~0u, x2, o);
            int y3 = __shfl_up_sync(~0u, x3, o);
            if (lane >= o) { x0 += y0; x1 += y1; x2 += y2; x3 += y3; }
        }
        if (lane == 31) { sh0[warp] = x0; sh1[warp] = x1; sh2[warp] = x2; sh3[warp] = x3; }
        __syncthreads();
        if (tid < 8) {
            int y0 = sh0[tid], y1 = sh1[tid], y2 = sh2[tid], y3 = sh3[tid];
            #pragma unroll
            for (int o = 1; o < 8; o <<= 1) {
                int z0 = __shfl_up_sync(0xFFu, y0, o);
                int z1 = __shfl_up_sync(0xFFu, y1, o);
                int z2 = __shfl_up_sync(0xFFu, y2, o);
                int z3 = __shfl_up_sync(0xFFu, y3, o);
                if (tid >= o) { y0 += z0; y1 += z1; y2 += z2; y3 += z3; }
            }
            sh0[tid] = y0; sh1[tid] = y1; sh2[tid] = y2; sh3[tid] = y3;
        }
        __syncthreads();
        int b1 = x1 - t1 + (warp ? sh1[warp - 1] : 0) + c1;
        int b2 = x2 - t2 + (warp ? sh2[warp - 1] : 0) + c2;
        int b3 = x3 - t3 + (warp ? sh3[warp - 1] : 0) + c3;
        #pragma unroll
        for (int k = 0; k < 4; k++) {
            int w = base + tid * 4 + k;
            if (w < WMAX) {
                lvlArr[w]  = lv[k];
                contArr[w] = (lv[k] == 0) ? b1 : (lv[k] == 1) ? b2 : b3;
            }
            b1 += f1[k]; b2 += f2[k]; b3 += f3[k];
        }
        c0 += sh0[7]; c1 += sh1[7]; c2 += sh2[7]; c3 += sh3[7];
        __syncthreads();
    }
    if (tid == 0) {
        g_nwin[3 * s + 0] = c1;
        g_nwin[3 * s + 1] = c2;
        g_nwin[3 * s + 2] = c3;
        if (s == 0) g_total = c0;
        __threadfence();
        int prev = atomicAdd(&g_done, 1);
        if (prev == 1) {                       // second finisher computes offsets
            __threadfence();
            long long M = *((volatile int*)&g_total);
            int nw[6];
            #pragma unroll
            for (int q = 0; q < 6; q++) nw[q] = *((volatile int*)&g_nwin[q]);
            long long o = 0;
            g_off[0] = 0;       o = M * 192;          // feats
            g_off[1] = o;       o += M * 4;           // coords
            const int T[3] = {16, 32, 48};
            for (int ss = 0; ss < 2; ss++) {
                for (int d = 0; d < 3; d++) { g_off[2 + 6 * ss + d] = o; o += (long long)nw[3 * ss + d] * T[d] * 192; }
                for (int d = 0; d < 3; d++) { g_off[5 + 6 * ss + d] = o; o += (long long)nw[3 * ss + d] * T[d]; }
            }
            g_off[14] = o;
        }
    }
}

// ---- select body: decoupled-lookback compaction of keepF -> srcOf -----------------
#define SEL_THREADS 256
#define SEL_ITEMS   8
#define SEL_TILE    (SEL_THREADS * SEL_ITEMS)

__device__ void select_body(int n) {
    __shared__ int s_bid;
    __shared__ int s_wsum[8];
    __shared__ int s_base;
    if (threadIdx.x == 0) s_bid = atomicAdd(&g_ticket, 1);
    __syncthreads();
    int bid = s_bid;
    int base = bid * SEL_TILE;

    int flags[SEL_ITEMS];
    int cnt = 0;
    #pragma unroll
    for (int k = 0; k < SEL_ITEMS; k++) {
        int p = base + threadIdx.x * SEL_ITEMS + k;
        int f = (p < n) ? g_keepF[p] : 0;
        flags[k] = f; cnt += f;
    }
    int lane = threadIdx.x & 31, warp = threadIdx.x >> 5;
    int x = cnt;
    #pragma unroll
    for (int o = 1; o < 32; o <<= 1) { int y = __shfl_up_sync(~0u, x, o); if (lane >= o) x += y; }
    if (lane == 31) s_wsum[warp] = x;
    __syncthreads();
    if (threadIdx.x < 8) {
        int y = s_wsum[threadIdx.x];
        #pragma unroll
        for (int o = 1; o < 8; o <<= 1) { int z = __shfl_up_sync(0xFFu, y, o); if ((int)threadIdx.x >= o) y += z; }
        s_wsum[threadIdx.x] = y;
    }
    __syncthreads();
    int blockAgg   = s_wsum[7];
    int threadExcl = x - cnt + (warp ? s_wsum[warp - 1] : 0);

    if (threadIdx.x == 0) {
        if (bid == 0) {
            atomicExch(&g_status[0], ((unsigned long long)blockAgg << 2) | 2ull);
            s_base = 0;
        } else {
            atomicExch(&g_status[bid], ((unsigned long long)blockAgg << 2) | 1ull);
            int excl = 0;
            int look = bid - 1;
            while (true) {
                unsigned long long s;
                do { s = atomicAdd(&g_status[look], 0ull); } while ((s & 3ull) == 0ull);
                excl += (int)(s >> 2);
                if ((s & 3ull) == 2ull) break;
                look--;
            }
            atomicExch(&g_status[bid], ((unsigned long long)(excl + blockAgg) << 2) | 2ull);
            s_base = excl;
        }
    }
    __syncthreads();
    int pos = s_base + threadExcl;
    #pragma unroll
    for (int k = 0; k < SEL_ITEMS; k++) {
        if (flags[k]) g_srcOf[pos++] = base + threadIdx.x * SEL_ITEMS + k;
    }
}

// ---- fused meta (last 2 blocks) + select (rest) ------------------------------------
__global__ void k_metasel(int n) {
    if ((int)blockIdx.x >= (int)gridDim.x - 2) {
        meta_body((int)blockIdx.x - ((int)gridDim.x - 2));
        return;
    }
    select_body(n);
}

// ---- fused writer: feats+coords gather (first featBlocks) then pe+mask -------------
__global__ void k_write(const float4* __restrict__ fin, const int* __restrict__ coords,
                        float* __restrict__ out, int featBlocks) {
    if ((int)blockIdx.x < featBlocks) {
        int M = g_total;
        int idx = blockIdx.x * blockDim.x + threadIdx.x;
        int pos = idx / 48, c = idx - 48 * pos;
        if (pos >= M) return;
        int src = __ldg(&g_srcOf[pos]);
        float4 v = __ldcs(&fin[(long long)src * 48 + c]);
        __stcs(&((float4*)out)[(long long)pos * 48 + c], v);
        if (c == 0) {
            int4 cc = ((const int4*)coords)[src];
            float4* oc = (float4*)(out + g_off[1]);
            __stcs(&oc[pos], make_float4((float)cc.x, (float)cc.y, (float)cc.z, (float)cc.w));
        }
        return;
    }

    int b = (int)blockIdx.x - featBlocks;      // [0, 2*WMAX)
    int s = (b >= WMAX) ? 1 : 0;
    int w = b - s * WMAX;

    int cntSeg, cntF, segStart, lvl, conti;
    const int* arr;
    if (s == 0) {
        cntSeg = g_cnt0[w];
        cntF   = g_cntF0[w];
        if (cntF == 0) return;
        segStart = g_startA[w];
        lvl = g_lvl0[w]; conti = g_conti0[w];
        arr = g_arrA;
    } else {
        int cnt = g_cnt1c[w];
        if (cnt <= 0) return;
        cntF = min(cnt, targetOf(cnt));
        segStart = g_startB[w];
        lvl = g_lvl1[w]; conti = g_conti1[w];
        arr = g_arrB;
        cntSeg = cntF;        // first cntF sorted entries are the kept set
    }
    int T = tokensOf(lvl);
    long long pebase   = g_off[2 + 6 * s + lvl] + (long long)conti * T * 192;
    long long maskbase = g_off[5 + 6 * s + lvl] + (long long)conti * T;

    __shared__ int rowtab[48];
    int t = threadIdx.x;
    if (t < 32) {
        int lane = t;
        int nk = 0;
        for (int base = 0; base < cntSeg; base += 32) {
            int r = base + lane;
            int v = (r < cntSeg) ? arr[segStart + r] : -1;
            int f = (v >= 0) ? ((s == 0) ? g_keepF[v] : 1) : 0;
            unsigned m = __ballot_sync(~0u, f);
            if (f) {
                int slot = nk + __popc(m & ((1u << lane) - 1));
                int tb = g_tb[v];
                rowtab[slot] = s ? (tb >> 16) : (tb & 0xFFFF);
            }
            nk += __popc(m);
        }
        for (int p = nk + lane; p < T; p += 32) rowtab[p] = -1;
    }
    if (t < T) __stcs(&out[maskbase + t], (t >= cntF) ? 1.0f : 0.0f);
    __syncthreads();

    const float4* tab4 = (const float4*)g_tab;
    float4* o4 = (float4*)(out + pebase);
    int tot4 = T * 48;
    for (int j = t; j < tot4; j += blockDim.x) {
        int tt = j / 48, f4 = j - 48 * tt;
        int tb = rowtab[tt];
        float4 v = (tb >= 0) ? __ldg(&tab4[tb * 48 + f4]) : make_float4(0.f, 0.f, 0.f, 0.f);
        __stcs(&o4[j], v);
    }
}

// ---------------------------------------------------------------------------
extern "C" void kernel_launch(void* const* d_in, const int* in_sizes, int n_in,
                              void* d_out, int out_size) {
    const float* feats  = (const float*)d_in[0];
    const int*   coords = (const int*)d_in[1];
    float* out = (float*)d_out;

    int n = in_sizes[1] / 4;
    if (n > NV) n = NV;
    if (n <= 0) return;
    int nb = (n + 255) / 256;
    int wb = (WMAX + 7) / 8;     // 8 warps / block for per-window sort kernels

    int tabBlocks = max(nb, (400 * 192 + 255) / 256);

    k_tab<<<tabBlocks, 256>>>(n);                 // LUT + zero + keepF default
    k_wins<<<nb, 256>>>(coords, n);
    k_exscan2<<<2, 1024>>>();
    k_scat<<<nb, 256>>>(n);
    k_sw0<<<wb, 256>>>();
    k_sw1<<<wb, 256>>>();

    int selblk = (n + SEL_TILE - 1) / SEL_TILE;
    k_metasel<<<selblk + 2, SEL_THREADS>>>(n);

    int featBlocks = (n * 48 + 255) / 256;
    k_write<<<featBlocks + 2 * WMAX, 256>>>((const float4*)feats, coords, out, featBlocks);
}